// round 2
// baseline (speedup 1.0000x reference)
#include <cuda_runtime.h>
#include <math.h>

#define B_    32
#define N_    3136
#define DIM_  320
#define CN_   400
#define HEADS_ 5
#define NK_   196
#define DQ_   80
#define DV_   64

// ---------------- scratch (static device globals; no runtime allocation) ----
__device__ float g_xs[B_ * NK_ * CN_];    // after LN+GELU           (~10 MB)
__device__ float g_q [B_ * N_  * CN_];    // q projection            (~160 MB)
__device__ float g_k [B_ * NK_ * CN_];    // k projection            (~10 MB)
__device__ float g_v [B_ * NK_ * DIM_];   // v projection            (~8 MB)
__device__ float g_av[B_ * N_  * DIM_];   // attention output        (~128 MB)

__inline__ __device__ float warp_sum(float v) {
#pragma unroll
    for (int o = 16; o; o >>= 1) v += __shfl_xor_sync(0xffffffffu, v, o);
    return v;
}
__inline__ __device__ float warp_max(float v) {
#pragma unroll
    for (int o = 16; o; o >>= 1) v = fmaxf(v, __shfl_xor_sync(0xffffffffu, v, o));
    return v;
}

// ---------------- kernel A: dwconv(4x4,s4,depthwise) + 1x1 conv + LN + GELU --
__global__ __launch_bounds__(512) void sr_kernel(
    const float* __restrict__ x,   const float* __restrict__ dww,
    const float* __restrict__ dwb, const float* __restrict__ pww,
    const float* __restrict__ pwb, const float* __restrict__ lng,
    const float* __restrict__ lnb)
{
    int b  = blockIdx.x / NK_;
    int p  = blockIdx.x % NK_;
    int oh = p / 14, ow = p % 14;

    __shared__ float sdw[DIM_];
    __shared__ float spw[CN_];
    __shared__ float r1[16], r2[16];
    __shared__ float s_mu, s_rstd;

    int tid = threadIdx.x;

    // depthwise conv: one channel per thread (320 of 512 threads)
    if (tid < DIM_) {
        int c = tid;
        float acc = dwb[c];
        const float* xb = x + (size_t)b * N_ * DIM_ + c;
#pragma unroll
        for (int i = 0; i < 4; i++)
#pragma unroll
            for (int j = 0; j < 4; j++) {
                int n = (oh * 4 + i) * 56 + (ow * 4 + j);
                acc = fmaf(xb[(size_t)n * DIM_], dww[c * 16 + i * 4 + j], acc);
            }
        sdw[c] = acc;
    }
    __syncthreads();

    // pointwise 1x1 conv: warp per output channel (coalesced pw_w reads, L2 resident)
    int warp = tid >> 5, lane = tid & 31;
    for (int d = warp; d < CN_; d += 16) {
        const float* w = pww + (size_t)d * DIM_;
        float s = 0.f;
#pragma unroll
        for (int c = lane; c < DIM_; c += 32) s = fmaf(sdw[c], w[c], s);
        s = warp_sum(s);
        if (lane == 0) spw[d] = s + pwb[d];
    }
    __syncthreads();

    // LayerNorm over 400 channels
    float v = (tid < CN_) ? spw[tid] : 0.f;
    float s1 = warp_sum(v);
    float s2 = warp_sum(v * v);
    if (lane == 0) { r1[warp] = s1; r2[warp] = s2; }
    __syncthreads();
    if (tid == 0) {
        float a = 0.f, bq = 0.f;
#pragma unroll
        for (int w2 = 0; w2 < 16; w2++) { a += r1[w2]; bq += r2[w2]; }
        float mu  = a / (float)CN_;
        float var = bq / (float)CN_ - mu * mu;
        s_mu = mu;
        s_rstd = rsqrtf(var + 1e-5f);
    }
    __syncthreads();
    if (tid < CN_) {
        float y = (v - s_mu) * s_rstd * lng[tid] + lnb[tid];
        // exact GELU: 0.5*y*(1+erf(y/sqrt(2)))
        float g = 0.5f * y * (1.f + erff(y * 0.70710678118654752f));
        g_xs[(size_t)blockIdx.x * CN_ + tid] = g;
    }
}

// ---------------- tiled fp32 SGEMM: C[M,N] = A[M,K] @ B[K,N] (+bias) ---------
// BM=64, BN=64, BK=16, 256 threads, 4x4 microtile.
// Requirements used here: M%64==0, K%16==0, N%4==0 (N guarded per 64-tile).
__global__ __launch_bounds__(256) void sgemm_kernel(
    const float* __restrict__ A, const float* __restrict__ Bm,
    const float* __restrict__ bias, float* __restrict__ C,
    int M, int N, int K)
{
    __shared__ __align__(16) float sA[16][68];   // transposed A tile, padded
    __shared__ __align__(16) float sB[16][64];

    int tid = threadIdx.x;
    int tr = tid >> 4, tc = tid & 15;
    int row0 = blockIdx.x * 64;
    int col0 = blockIdx.y * 64;

    int la_r = tid >> 2;          // 0..63
    int la_k = (tid & 3) << 2;    // 0,4,8,12
    int lb_k = tid >> 4;          // 0..15
    int lb_c = (tid & 15) << 2;   // 0..60

    float acc[4][4] = {};

    for (int k0 = 0; k0 < K; k0 += 16) {
        float4 av = *reinterpret_cast<const float4*>(
            A + (size_t)(row0 + la_r) * K + k0 + la_k);
        sA[la_k + 0][la_r] = av.x;
        sA[la_k + 1][la_r] = av.y;
        sA[la_k + 2][la_r] = av.z;
        sA[la_k + 3][la_r] = av.w;

        int bc = col0 + lb_c;
        float4 bv = make_float4(0.f, 0.f, 0.f, 0.f);
        if (bc < N)   // N%4==0 and bc%4==0 => float4 fully in or out
            bv = *reinterpret_cast<const float4*>(
                Bm + (size_t)(k0 + lb_k) * N + bc);
        *reinterpret_cast<float4*>(&sB[lb_k][lb_c]) = bv;
        __syncthreads();

#pragma unroll
        for (int kk = 0; kk < 16; kk++) {
            float4 a4 = *reinterpret_cast<const float4*>(&sA[kk][tr << 2]);
            float4 b4 = *reinterpret_cast<const float4*>(&sB[kk][tc << 2]);
            float aa[4] = {a4.x, a4.y, a4.z, a4.w};
            float bb[4] = {b4.x, b4.y, b4.z, b4.w};
#pragma unroll
            for (int i = 0; i < 4; i++)
#pragma unroll
                for (int j = 0; j < 4; j++)
                    acc[i][j] = fmaf(aa[i], bb[j], acc[i][j]);
        }
        __syncthreads();
    }

    int ccol = col0 + (tc << 2);
    if (ccol < N) {
#pragma unroll
        for (int i = 0; i < 4; i++) {
            float4 o;
            o.x = acc[i][0]; o.y = acc[i][1]; o.z = acc[i][2]; o.w = acc[i][3];
            if (bias) {
                o.x += bias[ccol];     o.y += bias[ccol + 1];
                o.z += bias[ccol + 2]; o.w += bias[ccol + 3];
            }
            *reinterpret_cast<float4*>(
                C + (size_t)(row0 + (tr << 2) + i) * N + ccol) = o;
        }
    }
}

// ---------------- fused attention: per (b, h, 64-query tile) -----------------
// K/V/Q/S all in shared memory; Nk=196 (keys padded to 256 in smem).
__global__ __launch_bounds__(256) void attn_kernel(float scale)
{
    extern __shared__ float sm[];
    float* sQ = sm;                   // [64][81]
    float* sK = sQ + 64 * 81;         // [256][81]  (rows >=196 zeroed)
    float* sV = sK + 256 * 81;        // [196][65]
    float* sS = sV + 196 * 65;        // [64][197]

    int qt = blockIdx.x, h = blockIdx.y, b = blockIdx.z;
    int q0 = qt * 64;
    int tid = threadIdx.x;

    {
        const float* kb = g_k + (size_t)b * NK_ * CN_ + h * DQ_;
        for (int idx = tid; idx < 256 * DQ_; idx += 256) {
            int j = idx / DQ_, d = idx - j * DQ_;
            sK[j * 81 + d] = (j < NK_) ? kb[(size_t)j * CN_ + d] : 0.f;
        }
    }
    {
        const float* vb = g_v + (size_t)b * NK_ * DIM_ + h * DV_;
        for (int idx = tid; idx < NK_ * DV_; idx += 256) {
            int j = idx / DV_, d = idx - j * DV_;
            sV[j * 65 + d] = vb[(size_t)j * DIM_ + d];
        }
    }
    {
        const float* qb = g_q + (size_t)(b * N_ + q0) * CN_ + h * DQ_;
        for (int idx = tid; idx < 64 * DQ_; idx += 256) {
            int i = idx / DQ_, d = idx - i * DQ_;
            sQ[i * 81 + d] = qb[(size_t)i * CN_ + d];
        }
    }
    __syncthreads();

    int tr = tid >> 4, tc = tid & 15;

    // Phase 1: S = scale * Q @ K^T  (keys in 4 chunks of 64)
#pragma unroll
    for (int kc = 0; kc < 4; kc++) {
        int key0 = kc * 64 + (tc << 2);
        float acc[4][4] = {};
        for (int d = 0; d < DQ_; d++) {
            float a[4], bb[4];
#pragma unroll
            for (int i = 0; i < 4; i++) a[i]  = sQ[(tr * 4 + i) * 81 + d];
#pragma unroll
            for (int j = 0; j < 4; j++) bb[j] = sK[(key0 + j) * 81 + d];
#pragma unroll
            for (int i = 0; i < 4; i++)
#pragma unroll
                for (int j = 0; j < 4; j++)
                    acc[i][j] = fmaf(a[i], bb[j], acc[i][j]);
        }
#pragma unroll
        for (int j = 0; j < 4; j++) {
            int key = key0 + j;
            if (key < NK_) {
#pragma unroll
                for (int i = 0; i < 4; i++)
                    sS[(tr * 4 + i) * 197 + key] = acc[i][j] * scale;
            }
        }
    }
    __syncthreads();

    // Phase 2: softmax over the 196 keys, warp per row
    int warp = tid >> 5, lane = tid & 31;
    for (int r = warp; r < 64; r += 8) {
        float m = -1e30f;
        for (int c = lane; c < NK_; c += 32) m = fmaxf(m, sS[r * 197 + c]);
        m = warp_max(m);
        float s = 0.f;
        for (int c = lane; c < NK_; c += 32) {
            float e = __expf(sS[r * 197 + c] - m);
            sS[r * 197 + c] = e;
            s += e;
        }
        s = warp_sum(s);
        float inv = 1.f / s;
        for (int c = lane; c < NK_; c += 32) sS[r * 197 + c] *= inv;
    }
    __syncthreads();

    // Phase 3: O = S @ V  -> [64][64]
    {
        float acc[4][4] = {};
        for (int kk = 0; kk < NK_; kk++) {
            float a[4], bb[4];
#pragma unroll
            for (int i = 0; i < 4; i++) a[i]  = sS[(tr * 4 + i) * 197 + kk];
#pragma unroll
            for (int j = 0; j < 4; j++) bb[j] = sV[kk * 65 + (tc << 2) + j];
#pragma unroll
            for (int i = 0; i < 4; i++)
#pragma unroll
                for (int j = 0; j < 4; j++)
                    acc[i][j] = fmaf(a[i], bb[j], acc[i][j]);
        }
#pragma unroll
        for (int i = 0; i < 4; i++) {
            float* o = g_av + (size_t)(b * N_ + q0 + tr * 4 + i) * DIM_
                     + h * DV_ + (tc << 2);
#pragma unroll
            for (int j = 0; j < 4; j++) o[j] = acc[i][j];
        }
    }
}

// ---------------- launch -----------------------------------------------------
extern "C" void kernel_launch(void* const* d_in, const int* in_sizes, int n_in,
                              void* d_out, int out_size)
{
    const float* x   = (const float*)d_in[0];
    // d_in[1]=H, d_in[2]=W (int32, fixed 56x56)
    const float* dww = (const float*)d_in[3];
    const float* dwb = (const float*)d_in[4];
    const float* pww = (const float*)d_in[5];
    const float* pwb = (const float*)d_in[6];
    const float* lng = (const float*)d_in[7];
    const float* lnb = (const float*)d_in[8];
    const float* qw  = (const float*)d_in[9];
    const float* kw  = (const float*)d_in[10];
    const float* vw  = (const float*)d_in[11];
    const float* pjw = (const float*)d_in[12];
    const float* pjb = (const float*)d_in[13];
    float* out = (float*)d_out;

    float *pxs, *pq, *pk, *pv, *pav;
    cudaGetSymbolAddress((void**)&pxs, g_xs);
    cudaGetSymbolAddress((void**)&pq,  g_q);
    cudaGetSymbolAddress((void**)&pk,  g_k);
    cudaGetSymbolAddress((void**)&pv,  g_v);
    cudaGetSymbolAddress((void**)&pav, g_av);

    // 1. spatial reduction path -> g_xs [32*196, 400]
    sr_kernel<<<B_ * NK_, 512>>>(x, dww, dwb, pww, pwb, lng, lnb);

    // 2. q = x @ q_w : [100352, 400]
    sgemm_kernel<<<dim3(B_ * N_ / 64, (CN_ + 63) / 64), 256>>>(
        x, qw, nullptr, pq, B_ * N_, CN_, DIM_);

    // 3. k = xs @ k_w : [6272, 400]
    sgemm_kernel<<<dim3(B_ * NK_ / 64, (CN_ + 63) / 64), 256>>>(
        pxs, kw, nullptr, pk, B_ * NK_, CN_, CN_);

    // 4. v = xs @ v_w : [6272, 320]
    sgemm_kernel<<<dim3(B_ * NK_ / 64, (DIM_ + 63) / 64), 256>>>(
        pxs, vw, nullptr, pv, B_ * NK_, DIM_, CN_);

    // 5. fused attention -> g_av [100352, 320]
    const int attn_smem = (64 * 81 + 256 * 81 + 196 * 65 + 64 * 197) * 4; // 205072 B
    cudaFuncSetAttribute(attn_kernel,
                         cudaFuncAttributeMaxDynamicSharedMemorySize, attn_smem);
    attn_kernel<<<dim3(N_ / 64, HEADS_, B_), 256, attn_smem>>>(
        0.11180339887498949f /* 80^-0.5 */);

    // 6. out = av @ proj_w + proj_b : [100352, 320]
    sgemm_kernel<<<dim3(B_ * N_ / 64, (DIM_ + 63) / 64), 256>>>(
        pav, pjw, pjb, out, B_ * N_, DIM_, DIM_);
}

// round 4
// speedup vs baseline: 1.5930x; 1.5930x over previous
#include <cuda_runtime.h>
#include <math.h>
#include <cstdint>

#define B_    32
#define N_    3136
#define DIM_  320
#define CN_   400
#define HEADS_ 5
#define NK_   196
#define DQ_   80
#define DV_   64
#define KP_   224    // keys padded to multiple of 8 (and 32) for MMA

// ---------------- scratch (static device globals; no runtime allocation) ----
__device__ float g_xs[B_ * NK_ * CN_];
__device__ float g_q [B_ * N_  * CN_];
__device__ float g_k [B_ * NK_ * CN_];
__device__ float g_v [B_ * NK_ * DIM_];
__device__ float g_av[B_ * N_  * DIM_];
// transposed (tf32-rounded) weights: Wt[N,K] row-major
__device__ float g_wtq[CN_ * DIM_];
__device__ float g_wtk[CN_ * CN_];
__device__ float g_wtv[DIM_ * CN_];
__device__ float g_wtp[DIM_ * DIM_];

// ---------------- helpers ----------------------------------------------------
__device__ __forceinline__ float to_tf32(float x) {
    float y;
    asm("cvt.rna.tf32.f32 %0, %1;" : "=f"(y) : "f"(x));
    return y;
}
__device__ __forceinline__ uint32_t fu(float x) { return __float_as_uint(x); }

// D += A(16x8,row) * B(8x8,col)   tf32 inputs, f32 accum
__device__ __forceinline__ void mma8(float c[4],
                                     uint32_t a0, uint32_t a1, uint32_t a2, uint32_t a3,
                                     uint32_t b0, uint32_t b1) {
    asm volatile(
        "mma.sync.aligned.m16n8k8.row.col.f32.tf32.tf32.f32 "
        "{%0,%1,%2,%3}, {%4,%5,%6,%7}, {%8,%9}, {%0,%1,%2,%3};"
        : "+f"(c[0]), "+f"(c[1]), "+f"(c[2]), "+f"(c[3])
        : "r"(a0), "r"(a1), "r"(a2), "r"(a3), "r"(b0), "r"(b1));
}

__inline__ __device__ float warp_sum(float v) {
#pragma unroll
    for (int o = 16; o; o >>= 1) v += __shfl_xor_sync(0xffffffffu, v, o);
    return v;
}
__inline__ __device__ float warp_max(float v) {
#pragma unroll
    for (int o = 16; o; o >>= 1) v = fmaxf(v, __shfl_xor_sync(0xffffffffu, v, o));
    return v;
}

// ---------------- weight transpose + tf32 round: Wt[n*K+k] = W[k*N+n] --------
__global__ void transpose_kernel(const float* __restrict__ W, float* __restrict__ Wt,
                                 int K, int N) {
    int k = blockIdx.x * 256 + threadIdx.x;
    int n = blockIdx.y;
    if (k < K) Wt[(size_t)n * K + k] = to_tf32(W[(size_t)k * N + n]);
}

// ---------------- kernel A: dwconv(4x4,s4,depthwise) + 1x1 conv + LN + GELU --
__global__ __launch_bounds__(512) void sr_kernel(
    const float* __restrict__ x,   const float* __restrict__ dww,
    const float* __restrict__ dwb, const float* __restrict__ pww,
    const float* __restrict__ pwb, const float* __restrict__ lng,
    const float* __restrict__ lnb)
{
    int b  = blockIdx.x / NK_;
    int p  = blockIdx.x % NK_;
    int oh = p / 14, ow = p % 14;

    __shared__ float sdw[DIM_];
    __shared__ float spw[CN_];
    __shared__ float r1[16], r2[16];
    __shared__ float s_mu, s_rstd;

    int tid = threadIdx.x;
    if (tid < DIM_) {
        int c = tid;
        float acc = dwb[c];
        const float* xb = x + (size_t)b * N_ * DIM_ + c;
#pragma unroll
        for (int i = 0; i < 4; i++)
#pragma unroll
            for (int j = 0; j < 4; j++) {
                int n = (oh * 4 + i) * 56 + (ow * 4 + j);
                acc = fmaf(xb[(size_t)n * DIM_], dww[c * 16 + i * 4 + j], acc);
            }
        sdw[c] = acc;
    }
    __syncthreads();

    int warp = tid >> 5, lane = tid & 31;
    for (int d = warp; d < CN_; d += 16) {
        const float* w = pww + (size_t)d * DIM_;
        float s = 0.f;
#pragma unroll
        for (int c = lane; c < DIM_; c += 32) s = fmaf(sdw[c], w[c], s);
        s = warp_sum(s);
        if (lane == 0) spw[d] = s + pwb[d];
    }
    __syncthreads();

    float v = (tid < CN_) ? spw[tid] : 0.f;
    float s1 = warp_sum(v);
    float s2 = warp_sum(v * v);
    if (lane == 0) { r1[warp] = s1; r2[warp] = s2; }
    __syncthreads();
    if (tid == 0) {
        float a = 0.f, bq = 0.f;
#pragma unroll
        for (int w2 = 0; w2 < 16; w2++) { a += r1[w2]; bq += r2[w2]; }
        float mu  = a / (float)CN_;
        float var = bq / (float)CN_ - mu * mu;
        s_mu = mu;
        s_rstd = rsqrtf(var + 1e-5f);
    }
    __syncthreads();
    if (tid < CN_) {
        float y = (v - s_mu) * s_rstd * lng[tid] + lnb[tid];
        float g = 0.5f * y * (1.f + erff(y * 0.70710678118654752f));
        g_xs[(size_t)blockIdx.x * CN_ + tid] = g;
    }
}

// ---------------- HMMA tf32 GEMM: C[M,N] = A[M,K] @ Wt[N,K]^T (+bias) --------
// 128x128 tile, BK=32, 256 threads (8 warps, each 64x32 via m16n8k8).
// M % 128 == 0; N, K mult of 4 (zero-pad guards on N and K edges).
__global__ __launch_bounds__(256) void mma_gemm(
    const float* __restrict__ A, const float* __restrict__ Bt,
    const float* __restrict__ bias, float* __restrict__ C,
    int M, int N, int K)
{
    __shared__ float sA[128 * 36];
    __shared__ float sB[128 * 36];

    int tid = threadIdx.x;
    int lane = tid & 31, w = tid >> 5;
    int g = lane >> 2, t = lane & 3;
    int row0 = blockIdx.x * 128, n0 = blockIdx.y * 128;
    int wm = (w & 1) * 64, wn = (w >> 1) * 32;

    float acc[4][4][4] = {};

    for (int k0 = 0; k0 < K; k0 += 32) {
#pragma unroll
        for (int it = 0; it < 4; it++) {
            int idx = it * 256 + tid;
            int r = idx >> 3, c = (idx & 7) << 2;
            float4 va = make_float4(0.f, 0.f, 0.f, 0.f);
            if (k0 + c < K)
                va = *reinterpret_cast<const float4*>(A + (size_t)(row0 + r) * K + k0 + c);
            va.x = to_tf32(va.x); va.y = to_tf32(va.y);
            va.z = to_tf32(va.z); va.w = to_tf32(va.w);
            *reinterpret_cast<float4*>(&sA[r * 36 + c]) = va;

            float4 vb = make_float4(0.f, 0.f, 0.f, 0.f);
            if (n0 + r < N && k0 + c < K)
                vb = *reinterpret_cast<const float4*>(Bt + (size_t)(n0 + r) * K + k0 + c);
            *reinterpret_cast<float4*>(&sB[r * 36 + c]) = vb;
        }
        __syncthreads();

#pragma unroll
        for (int ks = 0; ks < 4; ks++) {
            uint32_t af[4][4], bf[4][2];
#pragma unroll
            for (int mi = 0; mi < 4; mi++) {
                int R = wm + mi * 16;
                af[mi][0] = fu(sA[(R + g)     * 36 + ks * 8 + t]);
                af[mi][1] = fu(sA[(R + 8 + g) * 36 + ks * 8 + t]);
                af[mi][2] = fu(sA[(R + g)     * 36 + ks * 8 + 4 + t]);
                af[mi][3] = fu(sA[(R + 8 + g) * 36 + ks * 8 + 4 + t]);
            }
#pragma unroll
            for (int nj = 0; nj < 4; nj++) {
                int Nb = wn + nj * 8;
                bf[nj][0] = fu(sB[(Nb + g) * 36 + ks * 8 + t]);
                bf[nj][1] = fu(sB[(Nb + g) * 36 + ks * 8 + 4 + t]);
            }
#pragma unroll
            for (int mi = 0; mi < 4; mi++)
#pragma unroll
                for (int nj = 0; nj < 4; nj++)
                    mma8(acc[mi][nj], af[mi][0], af[mi][1], af[mi][2], af[mi][3],
                         bf[nj][0], bf[nj][1]);
        }
        __syncthreads();
    }

#pragma unroll
    for (int mi = 0; mi < 4; mi++)
#pragma unroll
        for (int nj = 0; nj < 4; nj++) {
            int r = row0 + wm + mi * 16 + g;
            int c = n0 + wn + nj * 8 + 2 * t;
            if (c < N) {
                float b0 = bias ? bias[c]     : 0.f;
                float b1 = bias ? bias[c + 1] : 0.f;
                *reinterpret_cast<float2*>(C + (size_t)r * N + c) =
                    make_float2(acc[mi][nj][0] + b0, acc[mi][nj][1] + b1);
                *reinterpret_cast<float2*>(C + (size_t)(r + 8) * N + c) =
                    make_float2(acc[mi][nj][2] + b0, acc[mi][nj][3] + b1);
            }
        }
}

// ---------------- fused attention (HMMA): per (b, h, 64-query tile) ----------
// smem strides chosen for conflict-free fragment loads.
#define SQS 84
#define SKS 84
#define SVS 72
#define SSS 228
__global__ __launch_bounds__(256) void attn_kernel(float scale)
{
    extern __shared__ float sm[];
    float* sQ = sm;                     // [64][84]
    float* sK = sQ + 64 * SQS;          // [224][84] rows>=196 zero
    float* sV = sK + KP_ * SKS;         // [224][72] rows>=196 zero
    float* sS = sV + KP_ * SVS;         // [64][228]

    int qt = blockIdx.x, h = blockIdx.y, b = blockIdx.z;
    int q0 = qt * 64;
    int tid = threadIdx.x;
    int lane = tid & 31, w = tid >> 5;
    int g = lane >> 2, t = lane & 3;

    {
        const float* qb = g_q + (size_t)(b * N_ + q0) * CN_ + h * DQ_;
        for (int idx = tid; idx < 64 * DQ_; idx += 256) {
            int i = idx / DQ_, d = idx - i * DQ_;
            sQ[i * SQS + d] = to_tf32(qb[(size_t)i * CN_ + d]);
        }
        const float* kb = g_k + (size_t)b * NK_ * CN_ + h * DQ_;
        for (int idx = tid; idx < KP_ * DQ_; idx += 256) {
            int j = idx / DQ_, d = idx - j * DQ_;
            sK[j * SKS + d] = (j < NK_) ? to_tf32(kb[(size_t)j * CN_ + d]) : 0.f;
        }
        const float* vb = g_v + (size_t)b * NK_ * DIM_ + h * DV_;
        for (int idx = tid; idx < KP_ * DV_; idx += 256) {
            int j = idx / DV_, d = idx - j * DV_;
            sV[j * SVS + d] = (j < NK_) ? to_tf32(vb[(size_t)j * DIM_ + d]) : 0.f;
        }
    }
    __syncthreads();

    // Phase 1: S = scale * Q @ K^T  (warp: 32 q-rows x 56 keys)
    {
        int mp = (w & 1) * 32, nq = (w >> 1) * 56;
        float acc[2][7][4] = {};
#pragma unroll
        for (int ks = 0; ks < 10; ks++) {
            uint32_t af[2][4], bf[7][2];
#pragma unroll
            for (int mi = 0; mi < 2; mi++) {
                int R = mp + mi * 16;
                af[mi][0] = fu(sQ[(R + g)     * SQS + ks * 8 + t]);
                af[mi][1] = fu(sQ[(R + 8 + g) * SQS + ks * 8 + t]);
                af[mi][2] = fu(sQ[(R + g)     * SQS + ks * 8 + 4 + t]);
                af[mi][3] = fu(sQ[(R + 8 + g) * SQS + ks * 8 + 4 + t]);
            }
#pragma unroll
            for (int nj = 0; nj < 7; nj++) {
                int Nb = nq + nj * 8;
                bf[nj][0] = fu(sK[(Nb + g) * SKS + ks * 8 + t]);
                bf[nj][1] = fu(sK[(Nb + g) * SKS + ks * 8 + 4 + t]);
            }
#pragma unroll
            for (int mi = 0; mi < 2; mi++)
#pragma unroll
                for (int nj = 0; nj < 7; nj++)
                    mma8(acc[mi][nj], af[mi][0], af[mi][1], af[mi][2], af[mi][3],
                         bf[nj][0], bf[nj][1]);
        }
#pragma unroll
        for (int mi = 0; mi < 2; mi++)
#pragma unroll
            for (int nj = 0; nj < 7; nj++) {
                int r = mp + mi * 16 + g;
                int c = (w >> 1) * 56 + nj * 8 + 2 * t;
                sS[r * SSS + c]           = acc[mi][nj][0] * scale;
                sS[r * SSS + c + 1]       = acc[mi][nj][1] * scale;
                sS[(r + 8) * SSS + c]     = acc[mi][nj][2] * scale;
                sS[(r + 8) * SSS + c + 1] = acc[mi][nj][3] * scale;
            }
    }
    __syncthreads();

    // Phase 2: softmax over 196 keys (pad cols are exactly 0 from zeroed K and stay 0)
    for (int r = w; r < 64; r += 8) {
        float m = -1e30f;
        for (int c = lane; c < NK_; c += 32) m = fmaxf(m, sS[r * SSS + c]);
        m = warp_max(m);
        float s = 0.f;
        for (int c = lane; c < NK_; c += 32) {
            float e = __expf(sS[r * SSS + c] - m);
            sS[r * SSS + c] = e;
            s += e;
        }
        s = warp_sum(s);
        float inv = 1.f / s;
        for (int c = lane; c < NK_; c += 32)
            sS[r * SSS + c] = to_tf32(sS[r * SSS + c] * inv);
        // zero the pad columns so phase-3 operand is clean tf32 zero
        for (int c = NK_ + lane; c < KP_; c += 32) sS[r * SSS + c] = 0.f;
    }
    __syncthreads();

    // Phase 3: O = S @ V  (warp: 32 q-rows x 16 v-cols)
    {
        int mp = (w & 1) * 32, nq = (w >> 1) * 16;
        float acc[2][2][4] = {};
#pragma unroll
        for (int ks = 0; ks < KP_ / 8; ks++) {
            uint32_t af[2][4], bf[2][2];
#pragma unroll
            for (int mi = 0; mi < 2; mi++) {
                int R = mp + mi * 16;
                af[mi][0] = fu(sS[(R + g)     * SSS + ks * 8 + t]);
                af[mi][1] = fu(sS[(R + 8 + g) * SSS + ks * 8 + t]);
                af[mi][2] = fu(sS[(R + g)     * SSS + ks * 8 + 4 + t]);
                af[mi][3] = fu(sS[(R + 8 + g) * SSS + ks * 8 + 4 + t]);
            }
#pragma unroll
            for (int nj = 0; nj < 2; nj++) {
                int Nb = nq + nj * 8;
                bf[nj][0] = fu(sV[(ks * 8 + t)     * SVS + Nb + g]);
                bf[nj][1] = fu(sV[(ks * 8 + 4 + t) * SVS + Nb + g]);
            }
#pragma unroll
            for (int mi = 0; mi < 2; mi++)
#pragma unroll
                for (int nj = 0; nj < 2; nj++)
                    mma8(acc[mi][nj], af[mi][0], af[mi][1], af[mi][2], af[mi][3],
                         bf[nj][0], bf[nj][1]);
        }
#pragma unroll
        for (int mi = 0; mi < 2; mi++)
#pragma unroll
            for (int nj = 0; nj < 2; nj++) {
                int r  = q0 + mp + mi * 16 + g;
                int cc = h * DV_ + nq + nj * 8 + 2 * t;
                float* o0 = g_av + (size_t)(b * N_ + r) * DIM_ + cc;
                *reinterpret_cast<float2*>(o0) =
                    make_float2(acc[mi][nj][0], acc[mi][nj][1]);
                float* o1 = g_av + (size_t)(b * N_ + r + 8) * DIM_ + cc;
                *reinterpret_cast<float2*>(o1) =
                    make_float2(acc[mi][nj][2], acc[mi][nj][3]);
            }
    }
}

// ---------------- launch -----------------------------------------------------
extern "C" void kernel_launch(void* const* d_in, const int* in_sizes, int n_in,
                              void* d_out, int out_size)
{
    const float* x   = (const float*)d_in[0];
    const float* dww = (const float*)d_in[3];
    const float* dwb = (const float*)d_in[4];
    const float* pww = (const float*)d_in[5];
    const float* pwb = (const float*)d_in[6];
    const float* lng = (const float*)d_in[7];
    const float* lnb = (const float*)d_in[8];
    const float* qw  = (const float*)d_in[9];
    const float* kw  = (const float*)d_in[10];
    const float* vw  = (const float*)d_in[11];
    const float* pjw = (const float*)d_in[12];
    const float* pjb = (const float*)d_in[13];
    float* out = (float*)d_out;

    float *pxs, *pq, *pk, *pv, *pav, *pwtq, *pwtk, *pwtv, *pwtp;
    cudaGetSymbolAddress((void**)&pxs,  g_xs);
    cudaGetSymbolAddress((void**)&pq,   g_q);
    cudaGetSymbolAddress((void**)&pk,   g_k);
    cudaGetSymbolAddress((void**)&pv,   g_v);
    cudaGetSymbolAddress((void**)&pav,  g_av);
    cudaGetSymbolAddress((void**)&pwtq, g_wtq);
    cudaGetSymbolAddress((void**)&pwtk, g_wtk);
    cudaGetSymbolAddress((void**)&pwtv, g_wtv);
    cudaGetSymbolAddress((void**)&pwtp, g_wtp);

    // transpose + tf32-round weights
    transpose_kernel<<<dim3(2, CN_),  256>>>(qw,  pwtq, DIM_, CN_);
    transpose_kernel<<<dim3(2, CN_),  256>>>(kw,  pwtk, CN_,  CN_);
    transpose_kernel<<<dim3(2, DIM_), 256>>>(vw,  pwtv, CN_,  DIM_);
    transpose_kernel<<<dim3(2, DIM_), 256>>>(pjw, pwtp, DIM_, DIM_);

    // spatial reduction path -> g_xs [6272, 400]
    sr_kernel<<<B_ * NK_, 512>>>(x, dww, dwb, pww, pwb, lng, lnb);

    // q = x @ q_w : [100352, 400]
    mma_gemm<<<dim3(B_ * N_ / 128, 4), 256>>>(x,   pwtq, nullptr, pq, B_ * N_,  CN_,  DIM_);
    // k = xs @ k_w : [6272, 400]
    mma_gemm<<<dim3(B_ * NK_ / 128, 4), 256>>>(pxs, pwtk, nullptr, pk, B_ * NK_, CN_,  CN_);
    // v = xs @ v_w : [6272, 320]
    mma_gemm<<<dim3(B_ * NK_ / 128, 3), 256>>>(pxs, pwtv, nullptr, pv, B_ * NK_, DIM_, CN_);

    // fused attention -> g_av [100352, 320]
    const int attn_smem = (64 * SQS + KP_ * SKS + KP_ * SVS + 64 * SSS) * 4;  // 219648
    cudaFuncSetAttribute(attn_kernel,
                         cudaFuncAttributeMaxDynamicSharedMemorySize, attn_smem);
    attn_kernel<<<dim3(N_ / 64, HEADS_, B_), 256, attn_smem>>>(
        0.11180339887498949f /* 80^-0.5 */);

    // out = av @ proj_w + proj_b : [100352, 320]
    mma_gemm<<<dim3(B_ * N_ / 128, 3), 256>>>(pav, pwtp, pjb, out, B_ * N_, DIM_, DIM_);
}

// round 5
// speedup vs baseline: 1.7824x; 1.1189x over previous
#include <cuda_runtime.h>
#include <math.h>
#include <cstdint>

#define B_    32
#define N_    3136
#define DIM_  320
#define CN_   400
#define HEADS_ 5
#define NK_   196
#define DQ_   80
#define DV_   64
#define KP_   224    // keys padded to multiple of 32 for MMA

// ---------------- scratch (static device globals; no runtime allocation) ----
__device__ float g_xs[B_ * NK_ * CN_];
__device__ float g_q [B_ * N_  * CN_];
__device__ float g_k [B_ * NK_ * CN_];
__device__ float g_v [B_ * NK_ * DIM_];
__device__ float g_av[B_ * N_  * DIM_];
// transposed (tf32-rounded) weights: Wt[N,K] row-major
__device__ float g_wtq[CN_ * DIM_];
__device__ float g_wtk[CN_ * CN_];
__device__ float g_wtv[DIM_ * CN_];
__device__ float g_wtp[DIM_ * DIM_];

// ---------------- helpers ----------------------------------------------------
__device__ __forceinline__ float to_tf32(float x) {
    float y;
    asm("cvt.rna.tf32.f32 %0, %1;" : "=f"(y) : "f"(x));
    return y;
}
__device__ __forceinline__ uint32_t fu(float x) { return __float_as_uint(x); }
__device__ __forceinline__ uint32_t smem_u32(const void* p) {
    uint32_t a;
    asm("{ .reg .u64 t; cvta.to.shared.u64 t, %1; cvt.u32.u64 %0, t; }"
        : "=r"(a) : "l"(p));
    return a;
}

#define CPA(dst, src, sz) \
    asm volatile("cp.async.cg.shared.global [%0], [%1], 16, %2;" \
        :: "r"(dst), "l"(src), "r"(sz))
#define CPC() asm volatile("cp.async.commit_group;" ::: "memory")
#define CPW(n) asm volatile("cp.async.wait_group %0;" :: "n"(n) : "memory")

// D += A(16x8,row) * B(8x8,col)   tf32 inputs, f32 accum
__device__ __forceinline__ void mma8(float c[4],
                                     uint32_t a0, uint32_t a1, uint32_t a2, uint32_t a3,
                                     uint32_t b0, uint32_t b1) {
    asm volatile(
        "mma.sync.aligned.m16n8k8.row.col.f32.tf32.tf32.f32 "
        "{%0,%1,%2,%3}, {%4,%5,%6,%7}, {%8,%9}, {%0,%1,%2,%3};"
        : "+f"(c[0]), "+f"(c[1]), "+f"(c[2]), "+f"(c[3])
        : "r"(a0), "r"(a1), "r"(a2), "r"(a3), "r"(b0), "r"(b1));
}

__inline__ __device__ float warp_sum(float v) {
#pragma unroll
    for (int o = 16; o; o >>= 1) v += __shfl_xor_sync(0xffffffffu, v, o);
    return v;
}
__inline__ __device__ float warp_max(float v) {
#pragma unroll
    for (int o = 16; o; o >>= 1) v = fmaxf(v, __shfl_xor_sync(0xffffffffu, v, o));
    return v;
}

// ---------------- weight transpose + tf32 round: Wt[n*K+k] = W[k*N+n] --------
__global__ void transpose_kernel(const float* __restrict__ W, float* __restrict__ Wt,
                                 int K, int N) {
    int k = blockIdx.x * 256 + threadIdx.x;
    int n = blockIdx.y;
    if (k < K) Wt[(size_t)n * K + k] = to_tf32(W[(size_t)k * N + n]);
}

// ---------------- kernel A: dwconv(4x4,s4,depthwise) + 1x1 conv + LN + GELU --
__global__ __launch_bounds__(512) void sr_kernel(
    const float* __restrict__ x,   const float* __restrict__ dww,
    const float* __restrict__ dwb, const float* __restrict__ pww,
    const float* __restrict__ pwb, const float* __restrict__ lng,
    const float* __restrict__ lnb)
{
    int b  = blockIdx.x / NK_;
    int p  = blockIdx.x % NK_;
    int oh = p / 14, ow = p % 14;

    __shared__ float sdw[DIM_];
    __shared__ float spw[CN_];
    __shared__ float r1[16], r2[16];
    __shared__ float s_mu, s_rstd;

    int tid = threadIdx.x;
    if (tid < DIM_) {
        int c = tid;
        float acc = dwb[c];
        const float* xb = x + (size_t)b * N_ * DIM_ + c;
#pragma unroll
        for (int i = 0; i < 4; i++)
#pragma unroll
            for (int j = 0; j < 4; j++) {
                int n = (oh * 4 + i) * 56 + (ow * 4 + j);
                acc = fmaf(xb[(size_t)n * DIM_], dww[c * 16 + i * 4 + j], acc);
            }
        sdw[c] = acc;
    }
    __syncthreads();

    int warp = tid >> 5, lane = tid & 31;
    for (int d = warp; d < CN_; d += 16) {
        const float* w = pww + (size_t)d * DIM_;
        float s = 0.f;
#pragma unroll
        for (int c = lane; c < DIM_; c += 32) s = fmaf(sdw[c], w[c], s);
        s = warp_sum(s);
        if (lane == 0) spw[d] = s + pwb[d];
    }
    __syncthreads();

    float v = (tid < CN_) ? spw[tid] : 0.f;
    float s1 = warp_sum(v);
    float s2 = warp_sum(v * v);
    if (lane == 0) { r1[warp] = s1; r2[warp] = s2; }
    __syncthreads();
    if (tid == 0) {
        float a = 0.f, bq = 0.f;
#pragma unroll
        for (int w2 = 0; w2 < 16; w2++) { a += r1[w2]; bq += r2[w2]; }
        float mu  = a / (float)CN_;
        float var = bq / (float)CN_ - mu * mu;
        s_mu = mu;
        s_rstd = rsqrtf(var + 1e-5f);
    }
    __syncthreads();
    if (tid < CN_) {
        float y = (v - s_mu) * s_rstd * lng[tid] + lnb[tid];
        float g = 0.5f * y * (1.f + erff(y * 0.70710678118654752f));
        g_xs[(size_t)blockIdx.x * CN_ + tid] = g;
    }
}

// ---------------- HMMA tf32 GEMM, cp.async double-buffered -------------------
// C[M,N] = A[M,K] @ Wt[N,K]^T (+bias). 128x128 tile, BK=32, 256 threads.
// M % 128 == 0; K, N arbitrary (zero-fill via cp.async src-size).
#define GSTG (128 * 36)   // floats per tile buffer
__global__ __launch_bounds__(256) void mma_gemm(
    const float* __restrict__ A, const float* __restrict__ Bt,
    const float* __restrict__ bias, float* __restrict__ C,
    int M, int N, int K)
{
    extern __shared__ float sm[];
    uint32_t sbase = smem_u32(sm);

    int tid = threadIdx.x;
    int lane = tid & 31, w = tid >> 5;
    int g = lane >> 2, t = lane & 3;
    int row0 = blockIdx.x * 128, n0 = blockIdx.y * 128;
    int wm = (w & 1) * 64, wn = (w >> 1) * 32;
    int nIter = (K + 31) / 32;

    float acc[4][4][4] = {};

    // stage layout: [stage][A | B], each GSTG floats
    int lr = tid >> 3, lc = (tid & 7) << 2;   // this thread's 4 (row,col) slots
    int brow = n0 + lr;
    const float* srcB0 = Bt + (size_t)(brow < N ? brow : 0) * K;
    const float* srcA0 = A + (size_t)(row0 + lr) * K;

    {   // prologue: stage 0
        uint32_t base = sbase;
#pragma unroll
        for (int it = 0; it < 4; it++) {
            int r = lr + it * 32, c = lc;
            int kk = c;
            const float* sa = A + (size_t)(row0 + r) * K + (kk < K ? kk : 0);
            CPA(base + (r * 36 + c) * 4, sa, (kk < K) ? 16 : 0);
            int br = n0 + r;
            const float* sb = Bt + (size_t)(br < N ? br : 0) * K + (kk < K ? kk : 0);
            CPA(base + (GSTG + r * 36 + c) * 4, sb, (br < N && kk < K) ? 16 : 0);
        }
        CPC();
    }

    for (int i = 0; i < nIter; i++) {
        if (i + 1 < nIter) {
            int k0 = (i + 1) * 32;
            uint32_t base = sbase + ((i + 1) & 1) * (2 * GSTG) * 4;
#pragma unroll
            for (int it = 0; it < 4; it++) {
                int r = lr + it * 32, c = lc;
                int kk = k0 + c;
                const float* sa = A + (size_t)(row0 + r) * K + (kk < K ? kk : 0);
                CPA(base + (r * 36 + c) * 4, sa, (kk < K) ? 16 : 0);
                int br = n0 + r;
                const float* sb = Bt + (size_t)(br < N ? br : 0) * K + (kk < K ? kk : 0);
                CPA(base + (GSTG + r * 36 + c) * 4, sb, (br < N && kk < K) ? 16 : 0);
            }
            CPC();
            CPW(1);
        } else {
            CPW(0);
        }
        __syncthreads();

        const float* sA = sm + (i & 1) * 2 * GSTG;
        const float* sB = sA + GSTG;
#pragma unroll
        for (int ks = 0; ks < 4; ks++) {
            uint32_t af[4][4], bf[4][2];
#pragma unroll
            for (int mi = 0; mi < 4; mi++) {
                int R = wm + mi * 16;
                af[mi][0] = fu(to_tf32(sA[(R + g)     * 36 + ks * 8 + t]));
                af[mi][1] = fu(to_tf32(sA[(R + 8 + g) * 36 + ks * 8 + t]));
                af[mi][2] = fu(to_tf32(sA[(R + g)     * 36 + ks * 8 + 4 + t]));
                af[mi][3] = fu(to_tf32(sA[(R + 8 + g) * 36 + ks * 8 + 4 + t]));
            }
#pragma unroll
            for (int nj = 0; nj < 4; nj++) {
                int Nb = wn + nj * 8;
                bf[nj][0] = fu(sB[(Nb + g) * 36 + ks * 8 + t]);
                bf[nj][1] = fu(sB[(Nb + g) * 36 + ks * 8 + 4 + t]);
            }
#pragma unroll
            for (int mi = 0; mi < 4; mi++)
#pragma unroll
                for (int nj = 0; nj < 4; nj++)
                    mma8(acc[mi][nj], af[mi][0], af[mi][1], af[mi][2], af[mi][3],
                         bf[nj][0], bf[nj][1]);
        }
        __syncthreads();
    }
    (void)srcA0; (void)srcB0;

#pragma unroll
    for (int mi = 0; mi < 4; mi++)
#pragma unroll
        for (int nj = 0; nj < 4; nj++) {
            int r = row0 + wm + mi * 16 + g;
            int c = n0 + wn + nj * 8 + 2 * t;
            if (c < N) {
                float b0 = bias ? bias[c]     : 0.f;
                float b1 = bias ? bias[c + 1] : 0.f;
                *reinterpret_cast<float2*>(C + (size_t)r * N + c) =
                    make_float2(acc[mi][nj][0] + b0, acc[mi][nj][1] + b1);
                *reinterpret_cast<float2*>(C + (size_t)(r + 8) * N + c) =
                    make_float2(acc[mi][nj][2] + b0, acc[mi][nj][3] + b1);
            }
        }
}

// ---------------- fused attention (HMMA): per (b, h, 64-query tile) ----------
#define SQS 84
#define SKS 84
#define SVS 72
#define SSS 228
__global__ __launch_bounds__(256) void attn_kernel(float scale)
{
    extern __shared__ float sm[];
    float* sQ = sm;                     // [64][84]
    float* sK = sQ + 64 * SQS;          // [224][84] rows>=196 zero
    float* sV = sK + KP_ * SKS;         // [224][72] rows>=196 zero
    float* sS = sV + KP_ * SVS;         // [64][228]
    float* sRcp = sS + 64 * SSS;        // [64] reciprocal row sums

    int qt = blockIdx.x, h = blockIdx.y, b = blockIdx.z;
    int q0 = qt * 64;
    int tid = threadIdx.x;
    int lane = tid & 31, w = tid >> 5;
    int g = lane >> 2, t = lane & 3;

    {
        const float* qb = g_q + (size_t)(b * N_ + q0) * CN_ + h * DQ_;
        for (int idx = tid; idx < 64 * DQ_; idx += 256) {
            int i = idx / DQ_, d = idx - i * DQ_;
            sQ[i * SQS + d] = to_tf32(qb[(size_t)i * CN_ + d]);
        }
        const float* kb = g_k + (size_t)b * NK_ * CN_ + h * DQ_;
        for (int idx = tid; idx < KP_ * DQ_; idx += 256) {
            int j = idx / DQ_, d = idx - j * DQ_;
            sK[j * SKS + d] = (j < NK_) ? to_tf32(kb[(size_t)j * CN_ + d]) : 0.f;
        }
        const float* vb = g_v + (size_t)b * NK_ * DIM_ + h * DV_;
        for (int idx = tid; idx < KP_ * DV_; idx += 256) {
            int j = idx / DV_, d = idx - j * DV_;
            sV[j * SVS + d] = (j < NK_) ? to_tf32(vb[(size_t)j * DIM_ + d]) : 0.f;
        }
    }
    __syncthreads();

    // Phase 1: S = scale * Q @ K^T  (warp: 32 q-rows x 56 keys)
    {
        int mp = (w & 1) * 32, nq = (w >> 1) * 56;
        float acc[2][7][4] = {};
#pragma unroll
        for (int ks = 0; ks < 10; ks++) {
            uint32_t af[2][4], bf[7][2];
#pragma unroll
            for (int mi = 0; mi < 2; mi++) {
                int R = mp + mi * 16;
                af[mi][0] = fu(sQ[(R + g)     * SQS + ks * 8 + t]);
                af[mi][1] = fu(sQ[(R + 8 + g) * SQS + ks * 8 + t]);
                af[mi][2] = fu(sQ[(R + g)     * SQS + ks * 8 + 4 + t]);
                af[mi][3] = fu(sQ[(R + 8 + g) * SQS + ks * 8 + 4 + t]);
            }
#pragma unroll
            for (int nj = 0; nj < 7; nj++) {
                int Nb = nq + nj * 8;
                bf[nj][0] = fu(sK[(Nb + g) * SKS + ks * 8 + t]);
                bf[nj][1] = fu(sK[(Nb + g) * SKS + ks * 8 + 4 + t]);
            }
#pragma unroll
            for (int mi = 0; mi < 2; mi++)
#pragma unroll
                for (int nj = 0; nj < 7; nj++)
                    mma8(acc[mi][nj], af[mi][0], af[mi][1], af[mi][2], af[mi][3],
                         bf[nj][0], bf[nj][1]);
        }
#pragma unroll
        for (int mi = 0; mi < 2; mi++)
#pragma unroll
            for (int nj = 0; nj < 7; nj++) {
                int r = mp + mi * 16 + g;
                int c = (w >> 1) * 56 + nj * 8 + 2 * t;
                sS[r * SSS + c]           = acc[mi][nj][0] * scale;
                sS[r * SSS + c + 1]       = acc[mi][nj][1] * scale;
                sS[(r + 8) * SSS + c]     = acc[mi][nj][2] * scale;
                sS[(r + 8) * SSS + c + 1] = acc[mi][nj][3] * scale;
            }
    }
    __syncthreads();

    // Phase 2: softmax numerator only; store tf32(exp), keep 1/sum in sRcp
    for (int r = w; r < 64; r += 8) {
        float m = -1e30f;
        for (int c = 2 * lane; c < NK_; c += 64) {
            float2 v2 = *reinterpret_cast<const float2*>(&sS[r * SSS + c]);
            m = fmaxf(m, fmaxf(v2.x, v2.y));
        }
        m = warp_max(m);
        float s = 0.f;
        for (int c = 2 * lane; c < NK_; c += 64) {
            float2 v2 = *reinterpret_cast<const float2*>(&sS[r * SSS + c]);
            float e0 = __expf(v2.x - m), e1 = __expf(v2.y - m);
            s += e0 + e1;
            *reinterpret_cast<float2*>(&sS[r * SSS + c]) =
                make_float2(to_tf32(e0), to_tf32(e1));
        }
        s = warp_sum(s);
        if (lane == 0) sRcp[r] = 1.f / s;
        for (int c = NK_ + lane; c < KP_; c += 32) sS[r * SSS + c] = 0.f;
    }
    __syncthreads();

    // Phase 3: O = (S @ V) * rcp  (warp: 32 q-rows x 16 v-cols)
    {
        int mp = (w & 1) * 32, nq = (w >> 1) * 16;
        float acc[2][2][4] = {};
#pragma unroll
        for (int ks = 0; ks < KP_ / 8; ks++) {
            uint32_t af[2][4], bf[2][2];
#pragma unroll
            for (int mi = 0; mi < 2; mi++) {
                int R = mp + mi * 16;
                af[mi][0] = fu(sS[(R + g)     * SSS + ks * 8 + t]);
                af[mi][1] = fu(sS[(R + 8 + g) * SSS + ks * 8 + t]);
                af[mi][2] = fu(sS[(R + g)     * SSS + ks * 8 + 4 + t]);
                af[mi][3] = fu(sS[(R + 8 + g) * SSS + ks * 8 + 4 + t]);
            }
#pragma unroll
            for (int nj = 0; nj < 2; nj++) {
                int Nb = nq + nj * 8;
                bf[nj][0] = fu(sV[(ks * 8 + t)     * SVS + Nb + g]);
                bf[nj][1] = fu(sV[(ks * 8 + 4 + t) * SVS + Nb + g]);
            }
#pragma unroll
            for (int mi = 0; mi < 2; mi++)
#pragma unroll
                for (int nj = 0; nj < 2; nj++)
                    mma8(acc[mi][nj], af[mi][0], af[mi][1], af[mi][2], af[mi][3],
                         bf[nj][0], bf[nj][1]);
        }
#pragma unroll
        for (int mi = 0; mi < 2; mi++) {
            float rc0 = sRcp[mp + mi * 16 + g];
            float rc1 = sRcp[mp + mi * 16 + 8 + g];
#pragma unroll
            for (int nj = 0; nj < 2; nj++) {
                int r  = q0 + mp + mi * 16 + g;
                int cc = h * DV_ + nq + nj * 8 + 2 * t;
                float* o0 = g_av + (size_t)(b * N_ + r) * DIM_ + cc;
                *reinterpret_cast<float2*>(o0) =
                    make_float2(acc[mi][nj][0] * rc0, acc[mi][nj][1] * rc0);
                float* o1 = g_av + (size_t)(b * N_ + r + 8) * DIM_ + cc;
                *reinterpret_cast<float2*>(o1) =
                    make_float2(acc[mi][nj][2] * rc1, acc[mi][nj][3] * rc1);
            }
        }
    }
}

// ---------------- launch -----------------------------------------------------
extern "C" void kernel_launch(void* const* d_in, const int* in_sizes, int n_in,
                              void* d_out, int out_size)
{
    const float* x   = (const float*)d_in[0];
    const float* dww = (const float*)d_in[3];
    const float* dwb = (const float*)d_in[4];
    const float* pww = (const float*)d_in[5];
    const float* pwb = (const float*)d_in[6];
    const float* lng = (const float*)d_in[7];
    const float* lnb = (const float*)d_in[8];
    const float* qw  = (const float*)d_in[9];
    const float* kw  = (const float*)d_in[10];
    const float* vw  = (const float*)d_in[11];
    const float* pjw = (const float*)d_in[12];
    const float* pjb = (const float*)d_in[13];
    float* out = (float*)d_out;

    float *pxs, *pq, *pk, *pv, *pav, *pwtq, *pwtk, *pwtv, *pwtp;
    cudaGetSymbolAddress((void**)&pxs,  g_xs);
    cudaGetSymbolAddress((void**)&pq,   g_q);
    cudaGetSymbolAddress((void**)&pk,   g_k);
    cudaGetSymbolAddress((void**)&pv,   g_v);
    cudaGetSymbolAddress((void**)&pav,  g_av);
    cudaGetSymbolAddress((void**)&pwtq, g_wtq);
    cudaGetSymbolAddress((void**)&pwtk, g_wtk);
    cudaGetSymbolAddress((void**)&pwtv, g_wtv);
    cudaGetSymbolAddress((void**)&pwtp, g_wtp);

    // transpose + tf32-round weights
    transpose_kernel<<<dim3(2, CN_),  256>>>(qw,  pwtq, DIM_, CN_);
    transpose_kernel<<<dim3(2, CN_),  256>>>(kw,  pwtk, CN_,  CN_);
    transpose_kernel<<<dim3(2, DIM_), 256>>>(vw,  pwtv, CN_,  DIM_);
    transpose_kernel<<<dim3(2, DIM_), 256>>>(pjw, pwtp, DIM_, DIM_);

    // spatial reduction path -> g_xs [6272, 400]
    sr_kernel<<<B_ * NK_, 512>>>(x, dww, dwb, pww, pwb, lng, lnb);

    const int gemm_smem = 2 * 2 * GSTG * 4;   // 73728 B
    cudaFuncSetAttribute(mma_gemm, cudaFuncAttributeMaxDynamicSharedMemorySize, gemm_smem);

    // q = x @ q_w : [100352, 400]
    mma_gemm<<<dim3(B_ * N_ / 128, 4), 256, gemm_smem>>>(
        x, pwtq, nullptr, pq, B_ * N_, CN_, DIM_);
    // k = xs @ k_w : [6272, 400]
    mma_gemm<<<dim3(B_ * NK_ / 128, 4), 256, gemm_smem>>>(
        pxs, pwtk, nullptr, pk, B_ * NK_, CN_, CN_);
    // v = xs @ v_w : [6272, 320]
    mma_gemm<<<dim3(B_ * NK_ / 128, 3), 256, gemm_smem>>>(
        pxs, pwtv, nullptr, pv, B_ * NK_, DIM_, CN_);

    // fused attention -> g_av [100352, 320]
    const int attn_smem = (64 * SQS + KP_ * SKS + KP_ * SVS + 64 * SSS + 64) * 4;
    cudaFuncSetAttribute(attn_kernel,
                         cudaFuncAttributeMaxDynamicSharedMemorySize, attn_smem);
    attn_kernel<<<dim3(N_ / 64, HEADS_, B_), 256, attn_smem>>>(
        0.11180339887498949f /* 80^-0.5 */);

    // out = av @ proj_w + proj_b : [100352, 320]
    mma_gemm<<<dim3(B_ * N_ / 128, 3), 256, gemm_smem>>>(
        pav, pwtp, pjb, out, B_ * N_, DIM_, DIM_);
}

// round 6
// speedup vs baseline: 4.4906x; 2.5194x over previous
#include <cuda_runtime.h>
#include <cuda_fp16.h>
#include <math.h>
#include <cstdint>

#define B_    32
#define N_    3136
#define DIM_  320
#define CN_   400
#define HEADS_ 5
#define NK_   196
#define DQ_   80
#define DV_   64
#define KP_   224

// ---------------- scratch (static device globals; no runtime allocation) ----
__device__ __align__(16) __half g_xh[B_ * N_  * DIM_];   // x in fp16
__device__ __align__(16) __half g_xs[B_ * NK_ * CN_];
__device__ __align__(16) __half g_q [B_ * N_  * CN_];
__device__ __align__(16) __half g_k [B_ * NK_ * CN_];
__device__ __align__(16) __half g_v [B_ * NK_ * DIM_];
__device__ __align__(16) __half g_av[B_ * N_  * DIM_];
__device__ __align__(16) __half g_wtq[CN_ * DIM_];
__device__ __align__(16) __half g_wtk[CN_ * CN_];
__device__ __align__(16) __half g_wtv[DIM_ * CN_];
__device__ __align__(16) __half g_wtp[DIM_ * DIM_];

// ---------------- helpers ----------------------------------------------------
__device__ __forceinline__ uint32_t smem_u32(const void* p) {
    uint32_t a;
    asm("{ .reg .u64 t; cvta.to.shared.u64 t, %1; cvt.u32.u64 %0, t; }"
        : "=r"(a) : "l"(p));
    return a;
}
#define CPA(dst, src, sz) \
    asm volatile("cp.async.cg.shared.global [%0], [%1], 16, %2;" \
        :: "r"(dst), "l"(src), "r"(sz))
#define CPC() asm volatile("cp.async.commit_group;" ::: "memory")
#define CPW(n) asm volatile("cp.async.wait_group %0;" :: "n"(n) : "memory")

// D += A(16x16,row) * B(16x8,col)  fp16 inputs, f32 accum
__device__ __forceinline__ void mma16(float c[4],
                                      uint32_t a0, uint32_t a1, uint32_t a2, uint32_t a3,
                                      uint32_t b0, uint32_t b1) {
    asm volatile(
        "mma.sync.aligned.m16n8k16.row.col.f32.f16.f16.f32 "
        "{%0,%1,%2,%3}, {%4,%5,%6,%7}, {%8,%9}, {%0,%1,%2,%3};"
        : "+f"(c[0]), "+f"(c[1]), "+f"(c[2]), "+f"(c[3])
        : "r"(a0), "r"(a1), "r"(a2), "r"(a3), "r"(b0), "r"(b1));
}

__inline__ __device__ float warp_sum(float v) {
#pragma unroll
    for (int o = 16; o; o >>= 1) v += __shfl_xor_sync(0xffffffffu, v, o);
    return v;
}

// ---------------- x -> fp16 ---------------------------------------------------
__global__ void cvt_x(const float* __restrict__ x, __half* __restrict__ xh, int n8) {
    int i = blockIdx.x * 256 + threadIdx.x;
    if (i < n8) {
        float4 a = reinterpret_cast<const float4*>(x)[2 * i];
        float4 b = reinterpret_cast<const float4*>(x)[2 * i + 1];
        __half2 h[4] = { __floats2half2_rn(a.x, a.y), __floats2half2_rn(a.z, a.w),
                         __floats2half2_rn(b.x, b.y), __floats2half2_rn(b.z, b.w) };
        reinterpret_cast<uint4*>(xh)[i] = *reinterpret_cast<uint4*>(h);
    }
}

// ---------------- weight transpose -> fp16: Wt[n*K+k] = W[k*N+n] -------------
__global__ void transpose_kernel(const float* __restrict__ W, __half* __restrict__ Wt,
                                 int K, int N) {
    int k = blockIdx.x * 256 + threadIdx.x;
    int n = blockIdx.y;
    if (k < K) Wt[(size_t)n * K + k] = __float2half_rn(W[(size_t)k * N + n]);
}

// ---------------- dwconv + 1x1 conv + LN + GELU ------------------------------
__global__ __launch_bounds__(512) void sr_kernel(
    const float* __restrict__ x,   const float* __restrict__ dww,
    const float* __restrict__ dwb, const float* __restrict__ pww,
    const float* __restrict__ pwb, const float* __restrict__ lng,
    const float* __restrict__ lnb)
{
    int b  = blockIdx.x / NK_;
    int p  = blockIdx.x % NK_;
    int oh = p / 14, ow = p % 14;

    __shared__ float sdw[DIM_];
    __shared__ float spw[CN_];
    __shared__ float r1[16], r2[16];
    __shared__ float s_mu, s_rstd;

    int tid = threadIdx.x;
    if (tid < DIM_) {
        int c = tid;
        float acc = dwb[c];
        const float* xb = x + (size_t)b * N_ * DIM_ + c;
#pragma unroll
        for (int i = 0; i < 4; i++)
#pragma unroll
            for (int j = 0; j < 4; j++) {
                int n = (oh * 4 + i) * 56 + (ow * 4 + j);
                acc = fmaf(xb[(size_t)n * DIM_], dww[c * 16 + i * 4 + j], acc);
            }
        sdw[c] = acc;
    }
    __syncthreads();

    int warp = tid >> 5, lane = tid & 31;
    for (int d = warp; d < CN_; d += 16) {
        const float* w = pww + (size_t)d * DIM_;
        float s = 0.f;
#pragma unroll
        for (int c = lane; c < DIM_; c += 32) s = fmaf(sdw[c], w[c], s);
        s = warp_sum(s);
        if (lane == 0) spw[d] = s + pwb[d];
    }
    __syncthreads();

    float v = (tid < CN_) ? spw[tid] : 0.f;
    float s1 = warp_sum(v);
    float s2 = warp_sum(v * v);
    if (lane == 0) { r1[warp] = s1; r2[warp] = s2; }
    __syncthreads();
    if (tid == 0) {
        float a = 0.f, bq = 0.f;
#pragma unroll
        for (int w2 = 0; w2 < 16; w2++) { a += r1[w2]; bq += r2[w2]; }
        float mu  = a / (float)CN_;
        float var = bq / (float)CN_ - mu * mu;
        s_mu = mu;
        s_rstd = rsqrtf(var + 1e-5f);
    }
    __syncthreads();
    if (tid < CN_) {
        float y = (v - s_mu) * s_rstd * lng[tid] + lnb[tid];
        float g = 0.5f * y * (1.f + erff(y * 0.70710678118654752f));
        g_xs[(size_t)blockIdx.x * CN_ + tid] = __float2half_rn(g);
    }
}

// ---------------- fp16 HMMA GEMM, cp.async double-buffered -------------------
// C[M,N] = A[M,K] @ Wt[N,K]^T (+bias). 128x128 tile, BK=64 halves, 256 thr.
// M % 128 == 0, K % 8 == 0; N arbitrary. Output: half (Ch) or float+bias (Cf).
#define HST 72                 // halves per smem row
#define HTILE (128 * HST)      // halves per tile (9216)
__global__ __launch_bounds__(256, 2) void hgemm(
    const __half* __restrict__ A, const __half* __restrict__ Bt,
    const float* __restrict__ bias, float* __restrict__ Cf,
    __half* __restrict__ Ch, int M, int N, int K)
{
    extern __shared__ __half hsm[];
    uint32_t sbase = smem_u32(hsm);

    int tid = threadIdx.x;
    int lane = tid & 31, w = tid >> 5;
    int g = lane >> 2, t = lane & 3;
    int row0 = blockIdx.x * 128, n0 = blockIdx.y * 128;
    int wm = (w & 1) * 64, wn = (w >> 1) * 32;
    int nIter = (K + 63) / 64;

    float acc[4][4][4] = {};

    // stage: [A(HTILE) | B(HTILE)]; 2 stages
    auto load_stage = [&](int s, int k0) {
        uint32_t base = sbase + s * (2 * HTILE * 2);
#pragma unroll
        for (int it = 0; it < 4; it++) {
            int gr = tid + it * 256;
            int r = gr >> 3, c8 = (gr & 7) << 3;
            int kk = k0 + c8;
            const __half* sa = A + (size_t)(row0 + r) * K + (kk < K ? kk : 0);
            CPA(base + (r * HST + c8) * 2, sa, (kk < K) ? 16 : 0);
            int br = n0 + r;
            const __half* sb = Bt + (size_t)(br < N ? br : 0) * K + (kk < K ? kk : 0);
            CPA(base + HTILE * 2 + (r * HST + c8) * 2, sb, (br < N && kk < K) ? 16 : 0);
        }
        CPC();
    };

    load_stage(0, 0);
    for (int i = 0; i < nIter; i++) {
        if (i + 1 < nIter) { load_stage((i + 1) & 1, (i + 1) * 64); CPW(1); }
        else CPW(0);
        __syncthreads();

        const uint32_t* sA2 = reinterpret_cast<const uint32_t*>(hsm + (i & 1) * 2 * HTILE);
        const uint32_t* sB2 = sA2 + HTILE / 2;
#pragma unroll
        for (int ks = 0; ks < 4; ks++) {
            uint32_t af[4][4], bf[4][2];
#pragma unroll
            for (int mi = 0; mi < 4; mi++) {
                int R = wm + mi * 16;
                af[mi][0] = sA2[(R + g)     * 36 + ks * 8 + t];
                af[mi][1] = sA2[(R + 8 + g) * 36 + ks * 8 + t];
                af[mi][2] = sA2[(R + g)     * 36 + ks * 8 + 4 + t];
                af[mi][3] = sA2[(R + 8 + g) * 36 + ks * 8 + 4 + t];
            }
#pragma unroll
            for (int nj = 0; nj < 4; nj++) {
                int Nb = wn + nj * 8;
                bf[nj][0] = sB2[(Nb + g) * 36 + ks * 8 + t];
                bf[nj][1] = sB2[(Nb + g) * 36 + ks * 8 + 4 + t];
            }
#pragma unroll
            for (int mi = 0; mi < 4; mi++)
#pragma unroll
                for (int nj = 0; nj < 4; nj++)
                    mma16(acc[mi][nj], af[mi][0], af[mi][1], af[mi][2], af[mi][3],
                          bf[nj][0], bf[nj][1]);
        }
        __syncthreads();
    }

#pragma unroll
    for (int mi = 0; mi < 4; mi++)
#pragma unroll
        for (int nj = 0; nj < 4; nj++) {
            int r = row0 + wm + mi * 16 + g;
            int c = n0 + wn + nj * 8 + 2 * t;
            if (c < N) {
                if (Ch) {
                    *reinterpret_cast<__half2*>(Ch + (size_t)r * N + c) =
                        __floats2half2_rn(acc[mi][nj][0], acc[mi][nj][1]);
                    *reinterpret_cast<__half2*>(Ch + (size_t)(r + 8) * N + c) =
                        __floats2half2_rn(acc[mi][nj][2], acc[mi][nj][3]);
                } else {
                    float b0 = bias ? bias[c]     : 0.f;
                    float b1 = bias ? bias[c + 1] : 0.f;
                    *reinterpret_cast<float2*>(Cf + (size_t)r * N + c) =
                        make_float2(acc[mi][nj][0] + b0, acc[mi][nj][1] + b1);
                    *reinterpret_cast<float2*>(Cf + (size_t)(r + 8) * N + c) =
                        make_float2(acc[mi][nj][2] + b0, acc[mi][nj][3] + b1);
                }
            }
        }
}

// ---------------- fused attention (fp16 HMMA, register softmax) --------------
// smem halves layout (stride in half2 shown):
//  sQ  [64][88]   (44)   sK [224][88] (44)   sVt [64][232] (116)
//  sP  [64][232]  (116)  + f32 pmax[64][4], psum[64][4], sRcp[64]
#define OQ   0
#define OK_  5632
#define OVT  25344
#define OP   40192
#define OF32 55040      // halves offset of f32 region
__global__ __launch_bounds__(256, 2) void attn_kernel(float scale)
{
    extern __shared__ __half hs[];
    float* pmax = reinterpret_cast<float*>(hs + OF32);
    float* psum = pmax + 256;
    float* srcp = psum + 256;

    int qt = blockIdx.x, h = blockIdx.y, b = blockIdx.z;
    int q0 = qt * 64;
    int tid = threadIdx.x;
    int lane = tid & 31, w = tid >> 5;
    int g = lane >> 2, t = lane & 3;
    int wg = w >> 1;

    // zero V^T region (pad keys must be 0, and no NaN garbage)
    for (int i = tid; i < (64 * 232) / 8; i += 256)
        reinterpret_cast<uint4*>(hs + OVT)[i] = make_uint4(0, 0, 0, 0);
    __syncthreads();

    {   // loads
        const __half* qb = g_q + (size_t)(b * N_ + q0) * CN_ + h * DQ_;
        for (int idx = tid; idx < 640; idx += 256) {
            int r = idx / 10, c8 = (idx % 10) * 8;
            *reinterpret_cast<uint4*>(hs + OQ + r * 88 + c8) =
                *reinterpret_cast<const uint4*>(qb + (size_t)r * CN_ + c8);
        }
        const __half* kb = g_k + (size_t)b * NK_ * CN_ + h * DQ_;
        for (int idx = tid; idx < 2240; idx += 256) {
            int j = idx / 10, c8 = (idx % 10) * 8;
            uint4 v = make_uint4(0, 0, 0, 0);
            if (j < NK_) v = *reinterpret_cast<const uint4*>(kb + (size_t)j * CN_ + c8);
            *reinterpret_cast<uint4*>(hs + OK_ + j * 88 + c8) = v;
        }
        const __half* vb = g_v + (size_t)b * NK_ * DIM_ + h * DV_;
        for (int idx = tid; idx < NK_ * DV_; idx += 256) {
            int j = idx >> 6, d = idx & 63;
            hs[OVT + d * 232 + j] = vb[(size_t)j * DIM_ + d];
        }
    }
    __syncthreads();

    // Phase 1: S = Q @ K^T (fp32 regs). warp: rows mp..mp+31, keys nq..nq+55
    int mp = (w & 1) * 32, nq = (w >> 1) * 56;
    float acc[2][7][4] = {};
    {
        const uint32_t* sQ2 = reinterpret_cast<const uint32_t*>(hs + OQ);
        const uint32_t* sK2 = reinterpret_cast<const uint32_t*>(hs + OK_);
#pragma unroll
        for (int ks = 0; ks < 5; ks++) {
            uint32_t af[2][4], bf[7][2];
#pragma unroll
            for (int mi = 0; mi < 2; mi++) {
                int R = mp + mi * 16;
                af[mi][0] = sQ2[(R + g)     * 44 + ks * 8 + t];
                af[mi][1] = sQ2[(R + 8 + g) * 44 + ks * 8 + t];
                af[mi][2] = sQ2[(R + g)     * 44 + ks * 8 + 4 + t];
                af[mi][3] = sQ2[(R + 8 + g) * 44 + ks * 8 + 4 + t];
            }
#pragma unroll
            for (int nj = 0; nj < 7; nj++) {
                int Nb = nq + nj * 8;
                bf[nj][0] = sK2[(Nb + g) * 44 + ks * 8 + t];
                bf[nj][1] = sK2[(Nb + g) * 44 + ks * 8 + 4 + t];
            }
#pragma unroll
            for (int mi = 0; mi < 2; mi++)
#pragma unroll
                for (int nj = 0; nj < 7; nj++)
                    mma16(acc[mi][nj], af[mi][0], af[mi][1], af[mi][2], af[mi][3],
                          bf[nj][0], bf[nj][1]);
        }
    }

    // Register softmax. Thread rows: rA = mp+mi*16+g (c0,c1), rB = rA+8 (c2,c3)
    float mx[2][2];
#pragma unroll
    for (int mi = 0; mi < 2; mi++) {
        float ma = -1e30f, mb = -1e30f;
#pragma unroll
        for (int nj = 0; nj < 7; nj++) {
            int c = nq + nj * 8 + 2 * t;
            if (c < NK_) {
                ma = fmaxf(ma, fmaxf(acc[mi][nj][0], acc[mi][nj][1]) * scale);
                mb = fmaxf(mb, fmaxf(acc[mi][nj][2], acc[mi][nj][3]) * scale);
            }
        }
#pragma unroll
        for (int o = 1; o <= 2; o <<= 1) {
            ma = fmaxf(ma, __shfl_xor_sync(0xffffffffu, ma, o));
            mb = fmaxf(mb, __shfl_xor_sync(0xffffffffu, mb, o));
        }
        mx[mi][0] = ma; mx[mi][1] = mb;
        if (t == 0) {
            pmax[(mp + mi * 16 + g) * 4 + wg]     = ma;
            pmax[(mp + mi * 16 + 8 + g) * 4 + wg] = mb;
        }
    }
    __syncthreads();
#pragma unroll
    for (int mi = 0; mi < 2; mi++) {
        int rA = mp + mi * 16 + g, rB = rA + 8;
        float ma = fmaxf(fmaxf(pmax[rA * 4], pmax[rA * 4 + 1]),
                         fmaxf(pmax[rA * 4 + 2], pmax[rA * 4 + 3]));
        float mb = fmaxf(fmaxf(pmax[rB * 4], pmax[rB * 4 + 1]),
                         fmaxf(pmax[rB * 4 + 2], pmax[rB * 4 + 3]));
        float sa = 0.f, sb = 0.f;
#pragma unroll
        for (int nj = 0; nj < 7; nj++) {
            int c = nq + nj * 8 + 2 * t;
            if (c < NK_) {
                float e0 = __expf(acc[mi][nj][0] * scale - ma);
                float e1 = __expf(acc[mi][nj][1] * scale - ma);
                float e2 = __expf(acc[mi][nj][2] * scale - mb);
                float e3 = __expf(acc[mi][nj][3] * scale - mb);
                acc[mi][nj][0] = e0; acc[mi][nj][1] = e1;
                acc[mi][nj][2] = e2; acc[mi][nj][3] = e3;
                sa += e0 + e1; sb += e2 + e3;
            } else {
                acc[mi][nj][0] = acc[mi][nj][1] = 0.f;
                acc[mi][nj][2] = acc[mi][nj][3] = 0.f;
            }
        }
#pragma unroll
        for (int o = 1; o <= 2; o <<= 1) {
            sa += __shfl_xor_sync(0xffffffffu, sa, o);
            sb += __shfl_xor_sync(0xffffffffu, sb, o);
        }
        if (t == 0) { psum[rA * 4 + wg] = sa; psum[rB * 4 + wg] = sb; }
        mx[mi][0] = ma; mx[mi][1] = mb;   // keep (unused later, cheap)
    }
    __syncthreads();
    // write probs (fp16) + reciprocal sums
    {
        uint32_t* sP2 = reinterpret_cast<uint32_t*>(hs + OP);
#pragma unroll
        for (int mi = 0; mi < 2; mi++) {
            int rA = mp + mi * 16 + g, rB = rA + 8;
            if (wg == 0 && t == 0) {
                srcp[rA] = 1.f / (psum[rA * 4] + psum[rA * 4 + 1] +
                                  psum[rA * 4 + 2] + psum[rA * 4 + 3]);
                srcp[rB] = 1.f / (psum[rB * 4] + psum[rB * 4 + 1] +
                                  psum[rB * 4 + 2] + psum[rB * 4 + 3]);
            }
#pragma unroll
            for (int nj = 0; nj < 7; nj++) {
                int c2 = (nq >> 1) + nj * 4 + t;
                __half2 h0 = __floats2half2_rn(acc[mi][nj][0], acc[mi][nj][1]);
                __half2 h1 = __floats2half2_rn(acc[mi][nj][2], acc[mi][nj][3]);
                sP2[rA * 116 + c2] = *reinterpret_cast<uint32_t*>(&h0);
                sP2[rB * 116 + c2] = *reinterpret_cast<uint32_t*>(&h1);
            }
        }
    }
    __syncthreads();

    // Phase 3: O = (P @ V) * rcp. warp: rows mp..mp+31, cols nq3..nq3+15
    {
        int nq3 = (w >> 1) * 16;
        const uint32_t* sP2 = reinterpret_cast<const uint32_t*>(hs + OP);
        const uint32_t* sV2 = reinterpret_cast<const uint32_t*>(hs + OVT);
        float o3[2][2][4] = {};
#pragma unroll
        for (int ks = 0; ks < 14; ks++) {
            uint32_t af[2][4], bf[2][2];
#pragma unroll
            for (int mi = 0; mi < 2; mi++) {
                int R = mp + mi * 16;
                af[mi][0] = sP2[(R + g)     * 116 + ks * 8 + t];
                af[mi][1] = sP2[(R + 8 + g) * 116 + ks * 8 + t];
                af[mi][2] = sP2[(R + g)     * 116 + ks * 8 + 4 + t];
                af[mi][3] = sP2[(R + 8 + g) * 116 + ks * 8 + 4 + t];
            }
#pragma unroll
            for (int nj = 0; nj < 2; nj++) {
                int Nb = nq3 + nj * 8;
                bf[nj][0] = sV2[(Nb + g) * 116 + ks * 8 + t];
                bf[nj][1] = sV2[(Nb + g) * 116 + ks * 8 + 4 + t];
            }
#pragma unroll
            for (int mi = 0; mi < 2; mi++)
#pragma unroll
                for (int nj = 0; nj < 2; nj++)
                    mma16(o3[mi][nj], af[mi][0], af[mi][1], af[mi][2], af[mi][3],
                          bf[nj][0], bf[nj][1]);
        }
#pragma unroll
        for (int mi = 0; mi < 2; mi++) {
            int rA = mp + mi * 16 + g;
            float rc0 = srcp[rA], rc1 = srcp[rA + 8];
#pragma unroll
            for (int nj = 0; nj < 2; nj++) {
                int cc = h * DV_ + nq3 + nj * 8 + 2 * t;
                __half* o0 = g_av + (size_t)(b * N_ + q0 + rA) * DIM_ + cc;
                *reinterpret_cast<__half2*>(o0) =
                    __floats2half2_rn(o3[mi][nj][0] * rc0, o3[mi][nj][1] * rc0);
                __half* o1 = g_av + (size_t)(b * N_ + q0 + rA + 8) * DIM_ + cc;
                *reinterpret_cast<__half2*>(o1) =
                    __floats2half2_rn(o3[mi][nj][2] * rc1, o3[mi][nj][3] * rc1);
            }
        }
    }
}

// ---------------- launch -----------------------------------------------------
extern "C" void kernel_launch(void* const* d_in, const int* in_sizes, int n_in,
                              void* d_out, int out_size)
{
    const float* x   = (const float*)d_in[0];
    const float* dww = (const float*)d_in[3];
    const float* dwb = (const float*)d_in[4];
    const float* pww = (const float*)d_in[5];
    const float* pwb = (const float*)d_in[6];
    const float* lng = (const float*)d_in[7];
    const float* lnb = (const float*)d_in[8];
    const float* qw  = (const float*)d_in[9];
    const float* kw  = (const float*)d_in[10];
    const float* vw  = (const float*)d_in[11];
    const float* pjw = (const float*)d_in[12];
    const float* pjb = (const float*)d_in[13];
    float* out = (float*)d_out;

    __half *pxh, *pxs, *pq, *pk, *pv, *pav, *pwtq, *pwtk, *pwtv, *pwtp;
    cudaGetSymbolAddress((void**)&pxh,  g_xh);
    cudaGetSymbolAddress((void**)&pxs,  g_xs);
    cudaGetSymbolAddress((void**)&pq,   g_q);
    cudaGetSymbolAddress((void**)&pk,   g_k);
    cudaGetSymbolAddress((void**)&pv,   g_v);
    cudaGetSymbolAddress((void**)&pav,  g_av);
    cudaGetSymbolAddress((void**)&pwtq, g_wtq);
    cudaGetSymbolAddress((void**)&pwtk, g_wtk);
    cudaGetSymbolAddress((void**)&pwtv, g_wtv);
    cudaGetSymbolAddress((void**)&pwtp, g_wtp);

    int n8 = B_ * N_ * DIM_ / 8;
    cvt_x<<<(n8 + 255) / 256, 256>>>(x, pxh, n8);

    transpose_kernel<<<dim3(2, CN_),  256>>>(qw,  pwtq, DIM_, CN_);
    transpose_kernel<<<dim3(2, CN_),  256>>>(kw,  pwtk, CN_,  CN_);
    transpose_kernel<<<dim3(2, DIM_), 256>>>(vw,  pwtv, CN_,  DIM_);
    transpose_kernel<<<dim3(2, DIM_), 256>>>(pjw, pwtp, DIM_, DIM_);

    sr_kernel<<<B_ * NK_, 512>>>(x, dww, dwb, pww, pwb, lng, lnb);

    const int gemm_smem = 2 * 2 * HTILE * 2;   // 73728 B
    cudaFuncSetAttribute(hgemm, cudaFuncAttributeMaxDynamicSharedMemorySize, gemm_smem);

    // q = x @ q_w
    hgemm<<<dim3(B_ * N_ / 128, 4), 256, gemm_smem>>>(
        pxh, pwtq, nullptr, nullptr, pq, B_ * N_, CN_, DIM_);
    // k = xs @ k_w
    hgemm<<<dim3(B_ * NK_ / 128, 4), 256, gemm_smem>>>(
        pxs, pwtk, nullptr, nullptr, pk, B_ * NK_, CN_, CN_);
    // v = xs @ v_w
    hgemm<<<dim3(B_ * NK_ / 128, 3), 256, gemm_smem>>>(
        pxs, pwtv, nullptr, nullptr, pv, B_ * NK_, DIM_, CN_);

    // fused attention
    const int attn_smem = OF32 * 2 + (256 + 256 + 64) * 4;   // 112384 B
    cudaFuncSetAttribute(attn_kernel,
                         cudaFuncAttributeMaxDynamicSharedMemorySize, attn_smem);
    attn_kernel<<<dim3(N_ / 64, HEADS_, B_), 256, attn_smem>>>(
        0.11180339887498949f /* 80^-0.5 */);

    // out = av @ proj_w + proj_b  (f32 out)
    hgemm<<<dim3(B_ * N_ / 128, 3), 256, gemm_smem>>>(
        pav, pwtp, pjb, out, nullptr, B_ * N_, DIM_, DIM_);
}

// round 8
// speedup vs baseline: 4.4963x; 1.0013x over previous
#include <cuda_runtime.h>
#include <cuda_fp16.h>
#include <math.h>
#include <cstdint>

#define B_    32
#define N_    3136
#define DIM_  320
#define CN_   400
#define HEADS_ 5
#define NK_   196
#define DQ_   80
#define DV_   64
#define KP_   224

// ---------------- scratch (static device globals; no runtime allocation) ----
__device__ __align__(16) __half g_xh[B_ * N_  * DIM_];
__device__ __align__(16) __half g_xs[B_ * NK_ * CN_];
__device__ __align__(16) __half g_q [B_ * N_  * CN_];
__device__ __align__(16) __half g_kv[B_ * NK_ * 720];      // k(400) | v(320)
__device__ __align__(16) __half g_av[B_ * N_  * DIM_];
__device__ __align__(16) __half g_wtq[CN_ * DIM_];         // [400][320]
__device__ __align__(16) __half g_wtkv[720 * CN_];         // [720][400]
__device__ __align__(16) __half g_wtp[DIM_ * DIM_];        // [320][320]

// ---------------- helpers ----------------------------------------------------
__device__ __forceinline__ uint32_t smem_u32(const void* p) {
    uint32_t a;
    asm("{ .reg .u64 t; cvta.to.shared.u64 t, %1; cvt.u32.u64 %0, t; }"
        : "=r"(a) : "l"(p));
    return a;
}
#define CPA(dst, src, sz) \
    asm volatile("cp.async.cg.shared.global [%0], [%1], 16, %2;" \
        :: "r"(dst), "l"(src), "r"(sz))
#define CPC() asm volatile("cp.async.commit_group;" ::: "memory")
#define CPW(n) asm volatile("cp.async.wait_group %0;" :: "n"(n) : "memory")

__device__ __forceinline__ void ldsm4(uint32_t r[4], uint32_t a) {
    asm volatile("ldmatrix.sync.aligned.m8n8.x4.shared.b16 {%0,%1,%2,%3}, [%4];"
        : "=r"(r[0]), "=r"(r[1]), "=r"(r[2]), "=r"(r[3]) : "r"(a));
}
__device__ __forceinline__ void ldsm2(uint32_t r[2], uint32_t a) {
    asm volatile("ldmatrix.sync.aligned.m8n8.x2.shared.b16 {%0,%1}, [%2];"
        : "=r"(r[0]), "=r"(r[1]) : "r"(a));
}
__device__ __forceinline__ void ldsm1(uint32_t& r, uint32_t a) {
    asm volatile("ldmatrix.sync.aligned.m8n8.x1.shared.b16 {%0}, [%1];"
        : "=r"(r) : "r"(a));
}

// D += A(16x16,row) * B(16x8,col)  fp16 inputs, f32 accum
__device__ __forceinline__ void mma16(float c[4],
                                      uint32_t a0, uint32_t a1, uint32_t a2, uint32_t a3,
                                      uint32_t b0, uint32_t b1) {
    asm volatile(
        "mma.sync.aligned.m16n8k16.row.col.f32.f16.f16.f32 "
        "{%0,%1,%2,%3}, {%4,%5,%6,%7}, {%8,%9}, {%0,%1,%2,%3};"
        : "+f"(c[0]), "+f"(c[1]), "+f"(c[2]), "+f"(c[3])
        : "r"(a0), "r"(a1), "r"(a2), "r"(a3), "r"(b0), "r"(b1));
}

__inline__ __device__ float warp_sum(float v) {
#pragma unroll
    for (int o = 16; o; o >>= 1) v += __shfl_xor_sync(0xffffffffu, v, o);
    return v;
}

// ---------------- x -> fp16 ---------------------------------------------------
__global__ void cvt_x(const float* __restrict__ x, __half* __restrict__ xh, int n8) {
    int i = blockIdx.x * 256 + threadIdx.x;
    if (i < n8) {
        float4 a = reinterpret_cast<const float4*>(x)[2 * i];
        float4 b = reinterpret_cast<const float4*>(x)[2 * i + 1];
        __half2 h[4] = { __floats2half2_rn(a.x, a.y), __floats2half2_rn(a.z, a.w),
                         __floats2half2_rn(b.x, b.y), __floats2half2_rn(b.z, b.w) };
        reinterpret_cast<uint4*>(xh)[i] = *reinterpret_cast<uint4*>(h);
    }
}

// ---------------- all weight transposes in one launch ------------------------
__global__ void transpose_all(const float* __restrict__ qw, const float* __restrict__ kw,
                              const float* __restrict__ vw, const float* __restrict__ pjw)
{
    int k = blockIdx.x * 256 + threadIdx.x;
    int n = blockIdx.y;
    int which = blockIdx.z;
    if (which == 0) {            // qw [320,400] -> wtq [400][320]
        if (k < DIM_ && n < CN_) g_wtq[(size_t)n * DIM_ + k] = __float2half_rn(qw[(size_t)k * CN_ + n]);
    } else if (which == 1) {     // kw [400,400] -> wtkv rows 0..399
        if (k < CN_ && n < CN_)  g_wtkv[(size_t)n * CN_ + k] = __float2half_rn(kw[(size_t)k * CN_ + n]);
    } else if (which == 2) {     // vw [400,320] -> wtkv rows 400..719
        if (k < CN_ && n < DIM_) g_wtkv[(size_t)(400 + n) * CN_ + k] = __float2half_rn(vw[(size_t)k * DIM_ + n]);
    } else {                     // pjw [320,320] -> wtp [320][320]
        if (k < DIM_ && n < DIM_) g_wtp[(size_t)n * DIM_ + k] = __float2half_rn(pjw[(size_t)k * DIM_ + n]);
    }
}

// ---------------- dwconv + 1x1 conv + LN + GELU ------------------------------
__global__ __launch_bounds__(512) void sr_kernel(
    const float* __restrict__ x,   const float* __restrict__ dww,
    const float* __restrict__ dwb, const float* __restrict__ pww,
    const float* __restrict__ pwb, const float* __restrict__ lng,
    const float* __restrict__ lnb)
{
    int b  = blockIdx.x / NK_;
    int p  = blockIdx.x % NK_;
    int oh = p / 14, ow = p % 14;

    __shared__ float sdw[DIM_];
    __shared__ float spw[CN_];
    __shared__ float r1[16], r2[16];
    __shared__ float s_mu, s_rstd;

    int tid = threadIdx.x;
    if (tid < DIM_) {
        int c = tid;
        float acc = dwb[c];
        const float* xb = x + (size_t)b * N_ * DIM_ + c;
#pragma unroll
        for (int i = 0; i < 4; i++)
#pragma unroll
            for (int j = 0; j < 4; j++) {
                int n = (oh * 4 + i) * 56 + (ow * 4 + j);
                acc = fmaf(xb[(size_t)n * DIM_], dww[c * 16 + i * 4 + j], acc);
            }
        sdw[c] = acc;
    }
    __syncthreads();

    int warp = tid >> 5, lane = tid & 31;
    for (int d = warp; d < CN_; d += 16) {
        const float* w = pww + (size_t)d * DIM_;
        float s = 0.f;
#pragma unroll
        for (int c = lane; c < DIM_; c += 32) s = fmaf(sdw[c], w[c], s);
        s = warp_sum(s);
        if (lane == 0) spw[d] = s + pwb[d];
    }
    __syncthreads();

    float v = (tid < CN_) ? spw[tid] : 0.f;
    float s1 = warp_sum(v);
    float s2 = warp_sum(v * v);
    if (lane == 0) { r1[warp] = s1; r2[warp] = s2; }
    __syncthreads();
    if (tid == 0) {
        float a = 0.f, bq = 0.f;
#pragma unroll
        for (int w2 = 0; w2 < 16; w2++) { a += r1[w2]; bq += r2[w2]; }
        float mu  = a / (float)CN_;
        float var = bq / (float)CN_ - mu * mu;
        s_mu = mu;
        s_rstd = rsqrtf(var + 1e-5f);
    }
    __syncthreads();
    if (tid < CN_) {
        float y = (v - s_mu) * s_rstd * lng[tid] + lnb[tid];
        float g = 0.5f * y * (1.f + erff(y * 0.70710678118654752f));
        g_xs[(size_t)blockIdx.x * CN_ + tid] = __float2half_rn(g);
    }
}

// ---------------- fp16 HMMA GEMM, cp.async + ldmatrix ------------------------
// C[M,N] = A[M,K] @ Bt[N,K]^T (+bias). 128x128 tile, BK=64 halves, 256 thr.
#define HST 72
#define HTILE (128 * HST)
__global__ __launch_bounds__(256, 2) void hgemm(
    const __half* __restrict__ A, const __half* __restrict__ Bt,
    const float* __restrict__ bias, float* __restrict__ Cf,
    __half* __restrict__ Ch, int M, int N, int K)
{
    extern __shared__ __half hsm[];
    uint32_t sbase = smem_u32(hsm);

    int tid = threadIdx.x;
    int lane = tid & 31, w = tid >> 5;
    int g = lane >> 2, t = lane & 3;
    int lrow = lane & 15, lkh = lane >> 4;
    int row0 = blockIdx.x * 128, n0 = blockIdx.y * 128;
    int wm = (w & 1) * 64, wn = (w >> 1) * 32;
    int nIter = (K + 63) / 64;

    float acc[4][4][4] = {};

    auto load_stage = [&](int s, int k0) {
        uint32_t base = sbase + s * (2 * HTILE * 2);
#pragma unroll
        for (int it = 0; it < 4; it++) {
            int gr = tid + it * 256;
            int r = gr >> 3, c8 = (gr & 7) << 3;
            int kk = k0 + c8;
            const __half* sa = A + (size_t)(row0 + r) * K + (kk < K ? kk : 0);
            CPA(base + (r * HST + c8) * 2, sa, (kk < K) ? 16 : 0);
            int br = n0 + r;
            const __half* sb = Bt + (size_t)(br < N ? br : 0) * K + (kk < K ? kk : 0);
            CPA(base + HTILE * 2 + (r * HST + c8) * 2, sb, (br < N && kk < K) ? 16 : 0);
        }
        CPC();
    };

    load_stage(0, 0);
    for (int i = 0; i < nIter; i++) {
        if (i + 1 < nIter) { load_stage((i + 1) & 1, (i + 1) * 64); CPW(1); }
        else CPW(0);
        __syncthreads();

        uint32_t sbA = sbase + (i & 1) * (2 * HTILE * 2);
        uint32_t sbB = sbA + HTILE * 2;
#pragma unroll
        for (int ks = 0; ks < 4; ks++) {
            uint32_t af[4][4], bf0[4], bf1[4];
#pragma unroll
            for (int mi = 0; mi < 4; mi++)
                ldsm4(af[mi], sbA + ((wm + mi * 16 + lrow) * HST + ks * 16 + lkh * 8) * 2);
            ldsm4(bf0, sbB + ((wn + lane) * HST + ks * 16 + 0) * 2);
            ldsm4(bf1, sbB + ((wn + lane) * HST + ks * 16 + 8) * 2);
#pragma unroll
            for (int mi = 0; mi < 4; mi++)
#pragma unroll
                for (int nj = 0; nj < 4; nj++)
                    mma16(acc[mi][nj], af[mi][0], af[mi][1], af[mi][2], af[mi][3],
                          bf0[nj], bf1[nj]);
        }
        __syncthreads();
    }

#pragma unroll
    for (int mi = 0; mi < 4; mi++)
#pragma unroll
        for (int nj = 0; nj < 4; nj++) {
            int r = row0 + wm + mi * 16 + g;
            int c = n0 + wn + nj * 8 + 2 * t;
            if (c < N) {
                if (Ch) {
                    *reinterpret_cast<__half2*>(Ch + (size_t)r * N + c) =
                        __floats2half2_rn(acc[mi][nj][0], acc[mi][nj][1]);
                    *reinterpret_cast<__half2*>(Ch + (size_t)(r + 8) * N + c) =
                        __floats2half2_rn(acc[mi][nj][2], acc[mi][nj][3]);
                } else {
                    float b0 = bias ? bias[c]     : 0.f;
                    float b1 = bias ? bias[c + 1] : 0.f;
                    *reinterpret_cast<float2*>(Cf + (size_t)r * N + c) =
                        make_float2(acc[mi][nj][0] + b0, acc[mi][nj][1] + b1);
                    *reinterpret_cast<float2*>(Cf + (size_t)(r + 8) * N + c) =
                        make_float2(acc[mi][nj][2] + b0, acc[mi][nj][3] + b1);
                }
            }
        }
}

// ---------------- fused attention (fp16 HMMA + ldmatrix, register softmax) ---
#define OQ   0
#define OK_  5632
#define OVT  25344
#define OP   40192
#define OF32 55040
__global__ __launch_bounds__(256, 2) void attn_kernel(float scale)
{
    extern __shared__ __half hs[];
    float* pmax = reinterpret_cast<float*>(hs + OF32);
    float* psum = pmax + 256;
    float* srcp = psum + 256;

    int qt = blockIdx.x, h = blockIdx.y, b = blockIdx.z;
    int q0 = qt * 64;
    int tid = threadIdx.x;
    int lane = tid & 31, w = tid >> 5;
    int g = lane >> 2, t = lane & 3;
    int lrow = lane & 15, lkh = lane >> 4;
    int wg = w >> 1;

    for (int i = tid; i < (64 * 232) / 8; i += 256)
        reinterpret_cast<uint4*>(hs + OVT)[i] = make_uint4(0, 0, 0, 0);
    __syncthreads();

    {   // loads (k/v from combined g_kv: row stride 720, k at h*80, v at 400+h*64)
        const __half* qb = g_q + (size_t)(b * N_ + q0) * CN_ + h * DQ_;
        for (int idx = tid; idx < 640; idx += 256) {
            int r = idx / 10, c8 = (idx % 10) * 8;
            *reinterpret_cast<uint4*>(hs + OQ + r * 88 + c8) =
                *reinterpret_cast<const uint4*>(qb + (size_t)r * CN_ + c8);
        }
        const __half* kb = g_kv + (size_t)b * NK_ * 720 + h * DQ_;
        for (int idx = tid; idx < 2240; idx += 256) {
            int j = idx / 10, c8 = (idx % 10) * 8;
            uint4 v = make_uint4(0, 0, 0, 0);
            if (j < NK_) v = *reinterpret_cast<const uint4*>(kb + (size_t)j * 720 + c8);
            *reinterpret_cast<uint4*>(hs + OK_ + j * 88 + c8) = v;
        }
        const __half* vb = g_kv + (size_t)b * NK_ * 720 + 400 + h * DV_;
        for (int idx = tid; idx < NK_ * DV_; idx += 256) {
            int j = idx >> 6, d = idx & 63;
            hs[OVT + d * 232 + j] = vb[(size_t)j * 720 + d];
        }
    }
    __syncthreads();

    // Phase 1: S = Q @ K^T. warp: rows mp..mp+31, keys nq..nq+55
    int mp = (w & 1) * 32, nq = (w >> 1) * 56;
    float acc[2][7][4] = {};
    {
        uint32_t sQb = smem_u32(hs + OQ);
        uint32_t sKb = smem_u32(hs + OK_);
#pragma unroll
        for (int ks = 0; ks < 5; ks++) {
            uint32_t af[2][4];
#pragma unroll
            for (int mi = 0; mi < 2; mi++)
                ldsm4(af[mi], sQb + ((mp + mi * 16 + lrow) * 88 + ks * 16 + lkh * 8) * 2);
            uint32_t bf[7][2];
#pragma unroll
            for (int kh = 0; kh < 2; kh++) {
                uint32_t b4[4], b2[2], b1;
                ldsm4(b4, sKb + ((nq + lane) * 88 + ks * 16 + kh * 8) * 2);
                ldsm2(b2, sKb + ((nq + 32 + (lane & 15)) * 88 + ks * 16 + kh * 8) * 2);
                ldsm1(b1, sKb + ((nq + 48 + (lane & 7)) * 88 + ks * 16 + kh * 8) * 2);
                bf[0][kh] = b4[0]; bf[1][kh] = b4[1]; bf[2][kh] = b4[2]; bf[3][kh] = b4[3];
                bf[4][kh] = b2[0]; bf[5][kh] = b2[1]; bf[6][kh] = b1;
            }
#pragma unroll
            for (int mi = 0; mi < 2; mi++)
#pragma unroll
                for (int nj = 0; nj < 7; nj++)
                    mma16(acc[mi][nj], af[mi][0], af[mi][1], af[mi][2], af[mi][3],
                          bf[nj][0], bf[nj][1]);
        }
    }

    // Register softmax
#pragma unroll
    for (int mi = 0; mi < 2; mi++) {
        float ma = -1e30f, mb = -1e30f;
#pragma unroll
        for (int nj = 0; nj < 7; nj++) {
            int c = nq + nj * 8 + 2 * t;
            if (c < NK_) {
                ma = fmaxf(ma, fmaxf(acc[mi][nj][0], acc[mi][nj][1]) * scale);
                mb = fmaxf(mb, fmaxf(acc[mi][nj][2], acc[mi][nj][3]) * scale);
            }
        }
#pragma unroll
        for (int o = 1; o <= 2; o <<= 1) {
            ma = fmaxf(ma, __shfl_xor_sync(0xffffffffu, ma, o));
            mb = fmaxf(mb, __shfl_xor_sync(0xffffffffu, mb, o));
        }
        if (t == 0) {
            pmax[(mp + mi * 16 + g) * 4 + wg]     = ma;
            pmax[(mp + mi * 16 + 8 + g) * 4 + wg] = mb;
        }
    }
    __syncthreads();
#pragma unroll
    for (int mi = 0; mi < 2; mi++) {
        int rA = mp + mi * 16 + g, rB = rA + 8;
        float ma = fmaxf(fmaxf(pmax[rA * 4], pmax[rA * 4 + 1]),
                         fmaxf(pmax[rA * 4 + 2], pmax[rA * 4 + 3]));
        float mb = fmaxf(fmaxf(pmax[rB * 4], pmax[rB * 4 + 1]),
                         fmaxf(pmax[rB * 4 + 2], pmax[rB * 4 + 3]));
        float sa = 0.f, sb = 0.f;
#pragma unroll
        for (int nj = 0; nj < 7; nj++) {
            int c = nq + nj * 8 + 2 * t;
            if (c < NK_) {
                float e0 = __expf(acc[mi][nj][0] * scale - ma);
                float e1 = __expf(acc[mi][nj][1] * scale - ma);
                float e2 = __expf(acc[mi][nj][2] * scale - mb);
                float e3 = __expf(acc[mi][nj][3] * scale - mb);
                acc[mi][nj][0] = e0; acc[mi][nj][1] = e1;
                acc[mi][nj][2] = e2; acc[mi][nj][3] = e3;
                sa += e0 + e1; sb += e2 + e3;
            } else {
                acc[mi][nj][0] = acc[mi][nj][1] = 0.f;
                acc[mi][nj][2] = acc[mi][nj][3] = 0.f;
            }
        }
#pragma unroll
        for (int o = 1; o <= 2; o <<= 1) {
            sa += __shfl_xor_sync(0xffffffffu, sa, o);
            sb += __shfl_xor_sync(0xffffffffu, sb, o);
        }
        if (t == 0) { psum[rA * 4 + wg] = sa; psum[rB * 4 + wg] = sb; }
    }
    __syncthreads();
    {
        uint32_t* sP2 = reinterpret_cast<uint32_t*>(hs + OP);
#pragma unroll
        for (int mi = 0; mi < 2; mi++) {
            int rA = mp + mi * 16 + g, rB = rA + 8;
            if (wg == 0 && t == 0) {
                srcp[rA] = 1.f / (psum[rA * 4] + psum[rA * 4 + 1] +
                                  psum[rA * 4 + 2] + psum[rA * 4 + 3]);
                srcp[rB] = 1.f / (psum[rB * 4] + psum[rB * 4 + 1] +
                                  psum[rB * 4 + 2] + psum[rB * 4 + 3]);
            }
#pragma unroll
            for (int nj = 0; nj < 7; nj++) {
                int c2 = (nq >> 1) + nj * 4 + t;
                __half2 h0 = __floats2half2_rn(acc[mi][nj][0], acc[mi][nj][1]);
                __half2 h1 = __floats2half2_rn(acc[mi][nj][2], acc[mi][nj][3]);
                sP2[rA * 116 + c2] = *reinterpret_cast<uint32_t*>(&h0);
                sP2[rB * 116 + c2] = *reinterpret_cast<uint32_t*>(&h1);
            }
        }
    }
    __syncthreads();

    // Phase 3: O = (P @ V) * rcp. warp: rows mp..mp+31, cols nq3..nq3+15
    {
        int nq3 = (w >> 1) * 16;
        uint32_t sPb = smem_u32(hs + OP);
        uint32_t sVb = smem_u32(hs + OVT);
        float o3[2][2][4] = {};
#pragma unroll
        for (int ks = 0; ks < 14; ks++) {
            uint32_t af[2][4], bv[4];
#pragma unroll
            for (int mi = 0; mi < 2; mi++)
                ldsm4(af[mi], sPb + ((mp + mi * 16 + lrow) * 232 + ks * 16 + lkh * 8) * 2);
            ldsm4(bv, sVb + ((nq3 + lrow) * 232 + ks * 16 + lkh * 8) * 2);
#pragma unroll
            for (int mi = 0; mi < 2; mi++) {
                mma16(o3[mi][0], af[mi][0], af[mi][1], af[mi][2], af[mi][3], bv[0], bv[2]);
                mma16(o3[mi][1], af[mi][0], af[mi][1], af[mi][2], af[mi][3], bv[1], bv[3]);
            }
        }
#pragma unroll
        for (int mi = 0; mi < 2; mi++) {
            int rA = mp + mi * 16 + g;
            float rc0 = srcp[rA], rc1 = srcp[rA + 8];
#pragma unroll
            for (int nj = 0; nj < 2; nj++) {
                int cc = h * DV_ + nq3 + nj * 8 + 2 * t;
                __half* o0 = g_av + (size_t)(b * N_ + q0 + rA) * DIM_ + cc;
                *reinterpret_cast<__half2*>(o0) =
                    __floats2half2_rn(o3[mi][nj][0] * rc0, o3[mi][nj][1] * rc0);
                __half* o1 = g_av + (size_t)(b * N_ + q0 + rA + 8) * DIM_ + cc;
                *reinterpret_cast<__half2*>(o1) =
                    __floats2half2_rn(o3[mi][nj][2] * rc1, o3[mi][nj][3] * rc1);
            }
        }
    }
}

// ---------------- launch -----------------------------------------------------
extern "C" void kernel_launch(void* const* d_in, const int* in_sizes, int n_in,
                              void* d_out, int out_size)
{
    const float* x   = (const float*)d_in[0];
    const float* dww = (const float*)d_in[3];
    const float* dwb = (const float*)d_in[4];
    const float* pww = (const float*)d_in[5];
    const float* pwb = (const float*)d_in[6];
    const float* lng = (const float*)d_in[7];
    const float* lnb = (const float*)d_in[8];
    const float* qw  = (const float*)d_in[9];
    const float* kw  = (const float*)d_in[10];
    const float* vw  = (const float*)d_in[11];
    const float* pjw = (const float*)d_in[12];
    const float* pjb = (const float*)d_in[13];
    float* out = (float*)d_out;

    __half *pxh, *pxs, *pq, *pkv, *pav, *pwtq, *pwtkv, *pwtp;
    cudaGetSymbolAddress((void**)&pxh,   g_xh);
    cudaGetSymbolAddress((void**)&pxs,   g_xs);
    cudaGetSymbolAddress((void**)&pq,    g_q);
    cudaGetSymbolAddress((void**)&pkv,   g_kv);
    cudaGetSymbolAddress((void**)&pav,   g_av);
    cudaGetSymbolAddress((void**)&pwtq,  g_wtq);
    cudaGetSymbolAddress((void**)&pwtkv, g_wtkv);
    cudaGetSymbolAddress((void**)&pwtp,  g_wtp);

    int n8 = B_ * N_ * DIM_ / 8;
    cvt_x<<<(n8 + 255) / 256, 256>>>(x, pxh, n8);

    transpose_all<<<dim3(2, CN_, 4), 256>>>(qw, kw, vw, pjw);

    sr_kernel<<<B_ * NK_, 512>>>(x, dww, dwb, pww, pwb, lng, lnb);

    const int gemm_smem = 2 * 2 * HTILE * 2;   // 73728 B
    cudaFuncSetAttribute(hgemm, cudaFuncAttributeMaxDynamicSharedMemorySize, gemm_smem);

    // q = x @ q_w : [100352, 400]
    hgemm<<<dim3(B_ * N_ / 128, 4), 256, gemm_smem>>>(
        pxh, pwtq, nullptr, nullptr, pq, B_ * N_, CN_, DIM_);
    // kv = xs @ [k_w | v_w] : [6272, 720]
    hgemm<<<dim3(B_ * NK_ / 128, 6), 256, gemm_smem>>>(
        pxs, pwtkv, nullptr, nullptr, pkv, B_ * NK_, 720, CN_);

    // fused attention -> g_av
    const int attn_smem = OF32 * 2 + (256 + 256 + 64) * 4;   // 112384 B
    cudaFuncSetAttribute(attn_kernel,
                         cudaFuncAttributeMaxDynamicSharedMemorySize, attn_smem);
    attn_kernel<<<dim3(N_ / 64, HEADS_, B_), 256, attn_smem>>>(
        0.11180339887498949f /* 80^-0.5 */);

    // out = av @ proj_w + proj_b  (f32 out)
    hgemm<<<dim3(B_ * N_ / 128, 3), 256, gemm_smem>>>(
        pav, pwtp, pjb, out, nullptr, B_ * N_, DIM_, DIM_);
}

// round 9
// speedup vs baseline: 4.5124x; 1.0036x over previous
#include <cuda_runtime.h>
#include <cuda_fp16.h>
#include <math.h>
#include <cstdint>

#define B_    32
#define N_    3136
#define DIM_  320
#define CN_   400
#define HEADS_ 5
#define NK_   196
#define DQ_   80
#define DV_   64
#define AQ_   128     // queries per attention block

// ---------------- scratch (static device globals; no runtime allocation) ----
__device__ __align__(16) __half g_xh[B_ * N_  * DIM_];
__device__ __align__(16) __half g_xs[B_ * NK_ * CN_];
__device__ __align__(16) __half g_q [B_ * N_  * CN_];
__device__ __align__(16) __half g_kv[B_ * NK_ * 720];      // k(400) | v(320)
__device__ __align__(16) __half g_av[B_ * N_  * DIM_];
__device__ __align__(16) __half g_wtq[CN_ * DIM_];
__device__ __align__(16) __half g_wtkv[720 * CN_];
__device__ __align__(16) __half g_wtp[DIM_ * DIM_];

// ---------------- helpers ----------------------------------------------------
__device__ __forceinline__ uint32_t smem_u32(const void* p) {
    uint32_t a;
    asm("{ .reg .u64 t; cvta.to.shared.u64 t, %1; cvt.u32.u64 %0, t; }"
        : "=r"(a) : "l"(p));
    return a;
}
#define CPA(dst, src, sz) \
    asm volatile("cp.async.cg.shared.global [%0], [%1], 16, %2;" \
        :: "r"(dst), "l"(src), "r"(sz))
#define CPC() asm volatile("cp.async.commit_group;" ::: "memory")
#define CPW(n) asm volatile("cp.async.wait_group %0;" :: "n"(n) : "memory")

__device__ __forceinline__ void ldsm4(uint32_t r[4], uint32_t a) {
    asm volatile("ldmatrix.sync.aligned.m8n8.x4.shared.b16 {%0,%1,%2,%3}, [%4];"
        : "=r"(r[0]), "=r"(r[1]), "=r"(r[2]), "=r"(r[3]) : "r"(a));
}
__device__ __forceinline__ void ldsm2(uint32_t r[2], uint32_t a) {
    asm volatile("ldmatrix.sync.aligned.m8n8.x2.shared.b16 {%0,%1}, [%2];"
        : "=r"(r[0]), "=r"(r[1]) : "r"(a));
}
__device__ __forceinline__ void ldsm1(uint32_t& r, uint32_t a) {
    asm volatile("ldmatrix.sync.aligned.m8n8.x1.shared.b16 {%0}, [%1];"
        : "=r"(r) : "r"(a));
}
__device__ __forceinline__ void ldsm4t(uint32_t r[4], uint32_t a) {
    asm volatile("ldmatrix.sync.aligned.m8n8.x4.trans.shared.b16 {%0,%1,%2,%3}, [%4];"
        : "=r"(r[0]), "=r"(r[1]), "=r"(r[2]), "=r"(r[3]) : "r"(a));
}

// D += A(16x16,row) * B(16x8,col)  fp16 inputs, f32 accum
__device__ __forceinline__ void mma16(float c[4],
                                      uint32_t a0, uint32_t a1, uint32_t a2, uint32_t a3,
                                      uint32_t b0, uint32_t b1) {
    asm volatile(
        "mma.sync.aligned.m16n8k16.row.col.f32.f16.f16.f32 "
        "{%0,%1,%2,%3}, {%4,%5,%6,%7}, {%8,%9}, {%0,%1,%2,%3};"
        : "+f"(c[0]), "+f"(c[1]), "+f"(c[2]), "+f"(c[3])
        : "r"(a0), "r"(a1), "r"(a2), "r"(a3), "r"(b0), "r"(b1));
}
// D += A(16x8,row) * B(8x8,col)  fp16 inputs, f32 accum
__device__ __forceinline__ void mma8k(float c[4], uint32_t a0, uint32_t a1, uint32_t b0) {
    asm volatile(
        "mma.sync.aligned.m16n8k8.row.col.f32.f16.f16.f32 "
        "{%0,%1,%2,%3}, {%4,%5}, {%6}, {%0,%1,%2,%3};"
        : "+f"(c[0]), "+f"(c[1]), "+f"(c[2]), "+f"(c[3])
        : "r"(a0), "r"(a1), "r"(b0));
}
__device__ __forceinline__ uint32_t packh2(float a, float b) {
    __half2 h = __floats2half2_rn(a, b);
    return *reinterpret_cast<uint32_t*>(&h);
}

__inline__ __device__ float warp_sum(float v) {
#pragma unroll
    for (int o = 16; o; o >>= 1) v += __shfl_xor_sync(0xffffffffu, v, o);
    return v;
}

// ---------------- x -> fp16 ---------------------------------------------------
__global__ void cvt_x(const float* __restrict__ x, __half* __restrict__ xh, int n8) {
    int i = blockIdx.x * 256 + threadIdx.x;
    if (i < n8) {
        float4 a = reinterpret_cast<const float4*>(x)[2 * i];
        float4 b = reinterpret_cast<const float4*>(x)[2 * i + 1];
        __half2 h[4] = { __floats2half2_rn(a.x, a.y), __floats2half2_rn(a.z, a.w),
                         __floats2half2_rn(b.x, b.y), __floats2half2_rn(b.z, b.w) };
        reinterpret_cast<uint4*>(xh)[i] = *reinterpret_cast<uint4*>(h);
    }
}

// ---------------- all weight transposes in one launch ------------------------
__global__ void transpose_all(const float* __restrict__ qw, const float* __restrict__ kw,
                              const float* __restrict__ vw, const float* __restrict__ pjw)
{
    int k = blockIdx.x * 256 + threadIdx.x;
    int n = blockIdx.y;
    int which = blockIdx.z;
    if (which == 0) {
        if (k < DIM_ && n < CN_) g_wtq[(size_t)n * DIM_ + k] = __float2half_rn(qw[(size_t)k * CN_ + n]);
    } else if (which == 1) {
        if (k < CN_ && n < CN_)  g_wtkv[(size_t)n * CN_ + k] = __float2half_rn(kw[(size_t)k * CN_ + n]);
    } else if (which == 2) {
        if (k < CN_ && n < DIM_) g_wtkv[(size_t)(400 + n) * CN_ + k] = __float2half_rn(vw[(size_t)k * DIM_ + n]);
    } else {
        if (k < DIM_ && n < DIM_) g_wtp[(size_t)n * DIM_ + k] = __float2half_rn(pjw[(size_t)k * DIM_ + n]);
    }
}

// ---------------- dwconv + 1x1 conv + LN + GELU ------------------------------
__global__ __launch_bounds__(512) void sr_kernel(
    const float* __restrict__ x,   const float* __restrict__ dww,
    const float* __restrict__ dwb, const float* __restrict__ pww,
    const float* __restrict__ pwb, const float* __restrict__ lng,
    const float* __restrict__ lnb)
{
    int b  = blockIdx.x / NK_;
    int p  = blockIdx.x % NK_;
    int oh = p / 14, ow = p % 14;

    __shared__ float sdw[DIM_];
    __shared__ float spw[CN_];
    __shared__ float r1[16], r2[16];
    __shared__ float s_mu, s_rstd;

    int tid = threadIdx.x;
    if (tid < DIM_) {
        int c = tid;
        float acc = dwb[c];
        const float* xb = x + (size_t)b * N_ * DIM_ + c;
#pragma unroll
        for (int i = 0; i < 4; i++)
#pragma unroll
            for (int j = 0; j < 4; j++) {
                int n = (oh * 4 + i) * 56 + (ow * 4 + j);
                acc = fmaf(xb[(size_t)n * DIM_], dww[c * 16 + i * 4 + j], acc);
            }
        sdw[c] = acc;
    }
    __syncthreads();

    int warp = tid >> 5, lane = tid & 31;
    for (int d = warp; d < CN_; d += 16) {
        const float* w = pww + (size_t)d * DIM_;
        float s = 0.f;
#pragma unroll
        for (int c = lane; c < DIM_; c += 32) s = fmaf(sdw[c], w[c], s);
        s = warp_sum(s);
        if (lane == 0) spw[d] = s + pwb[d];
    }
    __syncthreads();

    float v = (tid < CN_) ? spw[tid] : 0.f;
    float s1 = warp_sum(v);
    float s2 = warp_sum(v * v);
    if (lane == 0) { r1[warp] = s1; r2[warp] = s2; }
    __syncthreads();
    if (tid == 0) {
        float a = 0.f, bq = 0.f;
#pragma unroll
        for (int w2 = 0; w2 < 16; w2++) { a += r1[w2]; bq += r2[w2]; }
        float mu  = a / (float)CN_;
        float var = bq / (float)CN_ - mu * mu;
        s_mu = mu;
        s_rstd = rsqrtf(var + 1e-5f);
    }
    __syncthreads();
    if (tid < CN_) {
        float y = (v - s_mu) * s_rstd * lng[tid] + lnb[tid];
        float g = 0.5f * y * (1.f + erff(y * 0.70710678118654752f));
        g_xs[(size_t)blockIdx.x * CN_ + tid] = __float2half_rn(g);
    }
}

// ---------------- fp16 HMMA GEMM, 3-stage cp.async + ldmatrix ----------------
#define HST 72
#define HTILE (128 * HST)
__global__ __launch_bounds__(256, 2) void hgemm(
    const __half* __restrict__ A, const __half* __restrict__ Bt,
    const float* __restrict__ bias, float* __restrict__ Cf,
    __half* __restrict__ Ch, int M, int N, int K)
{
    extern __shared__ __half hsm[];
    uint32_t sbase = smem_u32(hsm);

    int tid = threadIdx.x;
    int lane = tid & 31, w = tid >> 5;
    int g = lane >> 2, t = lane & 3;
    int lrow = lane & 15, lkh = lane >> 4;
    int row0 = blockIdx.x * 128, n0 = blockIdx.y * 128;
    int wm = (w & 1) * 64, wn = (w >> 1) * 32;
    int nIter = (K + 63) / 64;

    float acc[4][4][4] = {};

    auto load_stage = [&](int s, int k0) {
        uint32_t base = sbase + s * (2 * HTILE * 2);
#pragma unroll
        for (int it = 0; it < 4; it++) {
            int gr = tid + it * 256;
            int r = gr >> 3, c8 = (gr & 7) << 3;
            int kk = k0 + c8;
            const __half* sa = A + (size_t)(row0 + r) * K + (kk < K ? kk : 0);
            CPA(base + (r * HST + c8) * 2, sa, (kk < K) ? 16 : 0);
            int br = n0 + r;
            const __half* sb = Bt + (size_t)(br < N ? br : 0) * K + (kk < K ? kk : 0);
            CPA(base + HTILE * 2 + (r * HST + c8) * 2, sb, (br < N && kk < K) ? 16 : 0);
        }
        CPC();
    };

    load_stage(0, 0);
    load_stage(1, 64);
    for (int i = 0; i < nIter; i++) {
        if (i + 2 < nIter) { load_stage((i + 2) % 3, (i + 2) * 64); CPW(2); }
        else CPW(0);
        __syncthreads();

        uint32_t sbA = sbase + (i % 3) * (2 * HTILE * 2);
        uint32_t sbB = sbA + HTILE * 2;
#pragma unroll
        for (int ks = 0; ks < 4; ks++) {
            uint32_t af[4][4], bf0[4], bf1[4];
#pragma unroll
            for (int mi = 0; mi < 4; mi++)
                ldsm4(af[mi], sbA + ((wm + mi * 16 + lrow) * HST + ks * 16 + lkh * 8) * 2);
            ldsm4(bf0, sbB + ((wn + lane) * HST + ks * 16 + 0) * 2);
            ldsm4(bf1, sbB + ((wn + lane) * HST + ks * 16 + 8) * 2);
#pragma unroll
            for (int mi = 0; mi < 4; mi++)
#pragma unroll
                for (int nj = 0; nj < 4; nj++)
                    mma16(acc[mi][nj], af[mi][0], af[mi][1], af[mi][2], af[mi][3],
                          bf0[nj], bf1[nj]);
        }
        __syncthreads();
    }

#pragma unroll
    for (int mi = 0; mi < 4; mi++)
#pragma unroll
        for (int nj = 0; nj < 4; nj++) {
            int r = row0 + wm + mi * 16 + g;
            int c = n0 + wn + nj * 8 + 2 * t;
            if (c < N) {
                if (Ch) {
                    *reinterpret_cast<__half2*>(Ch + (size_t)r * N + c) =
                        __floats2half2_rn(acc[mi][nj][0], acc[mi][nj][1]);
                    *reinterpret_cast<__half2*>(Ch + (size_t)(r + 8) * N + c) =
                        __floats2half2_rn(acc[mi][nj][2], acc[mi][nj][3]);
                } else {
                    float b0 = bias ? bias[c]     : 0.f;
                    float b1 = bias ? bias[c + 1] : 0.f;
                    *reinterpret_cast<float2*>(Cf + (size_t)r * N + c) =
                        make_float2(acc[mi][nj][0] + b0, acc[mi][nj][1] + b1);
                    *reinterpret_cast<float2*>(Cf + (size_t)(r + 8) * N + c) =
                        make_float2(acc[mi][nj][2] + b0, acc[mi][nj][3] + b1);
                }
            }
        }
}

// ---------------- fused attention v2: 128 queries, P-in-register split-K -----
// smem (halves): sQ[128][88]=11264, sK[224][88]=19712, sV[224][72]=16128
// then f32: sO[128][68], pmax[512], psum[512], rcp[128]
#define SQST 88
#define SKST 88
#define SVST 72
#define SOST 68
#define OQ   0
#define OK_  11264
#define OV   30976
#define OF32 47104
#define ATTN_SMEM (OF32 * 2 + (128 * SOST + 512 + 512 + 128) * 4)
__global__ __launch_bounds__(512, 1) void attn_kernel(float scale)
{
    extern __shared__ __half hs[];
    float* sO   = reinterpret_cast<float*>(hs + OF32);
    float* pmax = sO + 128 * SOST;
    float* psum = pmax + 512;
    float* srcp = psum + 512;

    int qt = blockIdx.x, h = blockIdx.y, b = blockIdx.z;
    int q0 = qt * AQ_;
    int tid = threadIdx.x;
    int lane = tid & 31, w = tid >> 5;
    int g = lane >> 2, t = lane & 3;
    int lrow = lane & 15, lkh = lane >> 4;
    int rg = w & 3, wg = w >> 2;
    int mp = rg * 32, nqk = wg * 56;

    // zero fp32 O accumulator
    for (int i = tid; i < 128 * SOST; i += 512) sO[i] = 0.f;

    {   // loads
        const __half* qb = g_q + ((size_t)(b * N_) + q0) * CN_ + h * DQ_;
        for (int idx = tid; idx < AQ_ * 10; idx += 512) {
            int r = idx / 10, c8 = (idx % 10) * 8;
            uint4 v = make_uint4(0, 0, 0, 0);
            if (q0 + r < N_) v = *reinterpret_cast<const uint4*>(qb + (size_t)r * CN_ + c8);
            *reinterpret_cast<uint4*>(hs + OQ + r * SQST + c8) = v;
        }
        const __half* kb = g_kv + (size_t)b * NK_ * 720 + h * DQ_;
        for (int idx = tid; idx < 224 * 10; idx += 512) {
            int j = idx / 10, c8 = (idx % 10) * 8;
            uint4 v = make_uint4(0, 0, 0, 0);
            if (j < NK_) v = *reinterpret_cast<const uint4*>(kb + (size_t)j * 720 + c8);
            *reinterpret_cast<uint4*>(hs + OK_ + j * SKST + c8) = v;
        }
        const __half* vb = g_kv + (size_t)b * NK_ * 720 + 400 + h * DV_;
        for (int idx = tid; idx < 224 * 8; idx += 512) {
            int j = idx / 8, c8 = (idx % 8) * 8;
            uint4 v = make_uint4(0, 0, 0, 0);
            if (j < NK_) v = *reinterpret_cast<const uint4*>(vb + (size_t)j * 720 + c8);
            *reinterpret_cast<uint4*>(hs + OV + j * SVST + c8) = v;
        }
    }
    __syncthreads();

    // Phase 1: S = Q @ K^T. warp: rows mp..mp+31, keys nqk..nqk+55
    float acc[2][7][4] = {};
    {
        uint32_t sQb = smem_u32(hs + OQ);
        uint32_t sKb = smem_u32(hs + OK_);
#pragma unroll
        for (int ks = 0; ks < 5; ks++) {
            uint32_t af[2][4];
#pragma unroll
            for (int mi = 0; mi < 2; mi++)
                ldsm4(af[mi], sQb + ((mp + mi * 16 + lrow) * SQST + ks * 16 + lkh * 8) * 2);
            uint32_t bf[7][2];
#pragma unroll
            for (int kh = 0; kh < 2; kh++) {
                uint32_t b4[4], b2[2], b1;
                ldsm4(b4, sKb + ((nqk + lane) * SKST + ks * 16 + kh * 8) * 2);
                ldsm2(b2, sKb + ((nqk + 32 + (lane & 15)) * SKST + ks * 16 + kh * 8) * 2);
                ldsm1(b1, sKb + ((nqk + 48 + (lane & 7)) * SKST + ks * 16 + kh * 8) * 2);
                bf[0][kh] = b4[0]; bf[1][kh] = b4[1]; bf[2][kh] = b4[2]; bf[3][kh] = b4[3];
                bf[4][kh] = b2[0]; bf[5][kh] = b2[1]; bf[6][kh] = b1;
            }
#pragma unroll
            for (int mi = 0; mi < 2; mi++)
#pragma unroll
                for (int nj = 0; nj < 7; nj++)
                    mma16(acc[mi][nj], af[mi][0], af[mi][1], af[mi][2], af[mi][3],
                          bf[nj][0], bf[nj][1]);
        }
    }

    // Register softmax (partial max per warp)
#pragma unroll
    for (int mi = 0; mi < 2; mi++) {
        float ma = -1e30f, mb = -1e30f;
#pragma unroll
        for (int nj = 0; nj < 7; nj++) {
            int c = nqk + nj * 8 + 2 * t;
            if (c < NK_) {
                ma = fmaxf(ma, fmaxf(acc[mi][nj][0], acc[mi][nj][1]) * scale);
                mb = fmaxf(mb, fmaxf(acc[mi][nj][2], acc[mi][nj][3]) * scale);
            }
        }
#pragma unroll
        for (int o = 1; o <= 2; o <<= 1) {
            ma = fmaxf(ma, __shfl_xor_sync(0xffffffffu, ma, o));
            mb = fmaxf(mb, __shfl_xor_sync(0xffffffffu, mb, o));
        }
        if (t == 0) {
            pmax[(mp + mi * 16 + g) * 4 + wg]     = ma;
            pmax[(mp + mi * 16 + 8 + g) * 4 + wg] = mb;
        }
    }
    __syncthreads();

    // exp + partial sums; keep probabilities in registers
#pragma unroll
    for (int mi = 0; mi < 2; mi++) {
        int rA = mp + mi * 16 + g, rB = rA + 8;
        float ma = fmaxf(fmaxf(pmax[rA * 4], pmax[rA * 4 + 1]),
                         fmaxf(pmax[rA * 4 + 2], pmax[rA * 4 + 3]));
        float mb = fmaxf(fmaxf(pmax[rB * 4], pmax[rB * 4 + 1]),
                         fmaxf(pmax[rB * 4 + 2], pmax[rB * 4 + 3]));
        float sa = 0.f, sb = 0.f;
#pragma unroll
        for (int nj = 0; nj < 7; nj++) {
            int c = nqk + nj * 8 + 2 * t;
            if (c < NK_) {
                float e0 = __expf(acc[mi][nj][0] * scale - ma);
                float e1 = __expf(acc[mi][nj][1] * scale - ma);
                float e2 = __expf(acc[mi][nj][2] * scale - mb);
                float e3 = __expf(acc[mi][nj][3] * scale - mb);
                acc[mi][nj][0] = e0; acc[mi][nj][1] = e1;
                acc[mi][nj][2] = e2; acc[mi][nj][3] = e3;
                sa += e0 + e1; sb += e2 + e3;
            } else {
                acc[mi][nj][0] = acc[mi][nj][1] = 0.f;
                acc[mi][nj][2] = acc[mi][nj][3] = 0.f;
            }
        }
#pragma unroll
        for (int o = 1; o <= 2; o <<= 1) {
            sa += __shfl_xor_sync(0xffffffffu, sa, o);
            sb += __shfl_xor_sync(0xffffffffu, sb, o);
        }
        if (t == 0) { psum[rA * 4 + wg] = sa; psum[rB * 4 + wg] = sb; }
    }

    // Pack P to fp16 A-fragments (c-fragment pairs == m16n8k8 a-fragment layout)
    uint32_t ppa[2][7], ppb[2][7];
#pragma unroll
    for (int mi = 0; mi < 2; mi++)
#pragma unroll
        for (int nj = 0; nj < 7; nj++) {
            ppa[mi][nj] = packh2(acc[mi][nj][0], acc[mi][nj][1]);
            ppb[mi][nj] = packh2(acc[mi][nj][2], acc[mi][nj][3]);
        }
    __syncthreads();

    if (tid < AQ_)
        srcp[tid] = 1.f / (psum[tid * 4] + psum[tid * 4 + 1] +
                           psum[tid * 4 + 2] + psum[tid * 4 + 3]);

    // Phase 3: split-K over this warp's 56 keys; B from V via ldmatrix.trans
    {
        uint32_t sVb = smem_u32(hs + OV);
#pragma unroll
        for (int vh = 0; vh < 2; vh++) {
            float o[2][4][4] = {};
#pragma unroll
            for (int ks = 0; ks < 7; ks++) {
                uint32_t bt[4];
                ldsm4t(bt, sVb + ((nqk + ks * 8 + (lane & 7)) * SVST
                                  + vh * 32 + (lane >> 3) * 8) * 2);
#pragma unroll
                for (int mi = 0; mi < 2; mi++)
#pragma unroll
                    for (int nj = 0; nj < 4; nj++)
                        mma8k(o[mi][nj], ppa[mi][ks], ppb[mi][ks], bt[nj]);
            }
#pragma unroll
            for (int mi = 0; mi < 2; mi++)
#pragma unroll
                for (int nj = 0; nj < 4; nj++) {
                    int row = mp + mi * 16 + g;
                    int col = vh * 32 + nj * 8 + 2 * t;
                    atomicAdd(&sO[row * SOST + col],           o[mi][nj][0]);
                    atomicAdd(&sO[row * SOST + col + 1],       o[mi][nj][1]);
                    atomicAdd(&sO[(row + 8) * SOST + col],     o[mi][nj][2]);
                    atomicAdd(&sO[(row + 8) * SOST + col + 1], o[mi][nj][3]);
                }
        }
    }
    __syncthreads();

    // scale by 1/sum and store
    for (int idx = tid; idx < AQ_ * 32; idx += 512) {
        int r = idx >> 5, c2 = idx & 31;
        if (q0 + r < N_) {
            float rc = srcp[r];
            float o0 = sO[r * SOST + 2 * c2]     * rc;
            float o1 = sO[r * SOST + 2 * c2 + 1] * rc;
            *reinterpret_cast<__half2*>(
                g_av + ((size_t)(b * N_) + q0 + r) * DIM_ + h * DV_ + 2 * c2) =
                __floats2half2_rn(o0, o1);
        }
    }
}

// ---------------- launch -----------------------------------------------------
extern "C" void kernel_launch(void* const* d_in, const int* in_sizes, int n_in,
                              void* d_out, int out_size)
{
    const float* x   = (const float*)d_in[0];
    const float* dww = (const float*)d_in[3];
    const float* dwb = (const float*)d_in[4];
    const float* pww = (const float*)d_in[5];
    const float* pwb = (const float*)d_in[6];
    const float* lng = (const float*)d_in[7];
    const float* lnb = (const float*)d_in[8];
    const float* qw  = (const float*)d_in[9];
    const float* kw  = (const float*)d_in[10];
    const float* vw  = (const float*)d_in[11];
    const float* pjw = (const float*)d_in[12];
    const float* pjb = (const float*)d_in[13];
    float* out = (float*)d_out;

    __half *pxh, *pxs, *pq, *pkv, *pav, *pwtq, *pwtkv, *pwtp;
    cudaGetSymbolAddress((void**)&pxh,   g_xh);
    cudaGetSymbolAddress((void**)&pxs,   g_xs);
    cudaGetSymbolAddress((void**)&pq,    g_q);
    cudaGetSymbolAddress((void**)&pkv,   g_kv);
    cudaGetSymbolAddress((void**)&pav,   g_av);
    cudaGetSymbolAddress((void**)&pwtq,  g_wtq);
    cudaGetSymbolAddress((void**)&pwtkv, g_wtkv);
    cudaGetSymbolAddress((void**)&pwtp,  g_wtp);

    int n8 = B_ * N_ * DIM_ / 8;
    cvt_x<<<(n8 + 255) / 256, 256>>>(x, pxh, n8);

    transpose_all<<<dim3(2, CN_, 4), 256>>>(qw, kw, vw, pjw);

    sr_kernel<<<B_ * NK_, 512>>>(x, dww, dwb, pww, pwb, lng, lnb);

    const int gemm_smem = 3 * 2 * HTILE * 2;   // 110592 B (3 stages)
    cudaFuncSetAttribute(hgemm, cudaFuncAttributeMaxDynamicSharedMemorySize, gemm_smem);

    // q = x @ q_w : [100352, 400]
    hgemm<<<dim3(B_ * N_ / 128, 4), 256, gemm_smem>>>(
        pxh, pwtq, nullptr, nullptr, pq, B_ * N_, CN_, DIM_);
    // kv = xs @ [k_w | v_w] : [6272, 720]
    hgemm<<<dim3(B_ * NK_ / 128, 6), 256, gemm_smem>>>(
        pxs, pwtkv, nullptr, nullptr, pkv, B_ * NK_, 720, CN_);

    // fused attention -> g_av   (ceil(3136/128)=25 query tiles)
    cudaFuncSetAttribute(attn_kernel,
                         cudaFuncAttributeMaxDynamicSharedMemorySize, ATTN_SMEM);
    attn_kernel<<<dim3((N_ + AQ_ - 1) / AQ_, HEADS_, B_), 512, ATTN_SMEM>>>(
        0.11180339887498949f /* 80^-0.5 */);

    // out = av @ proj_w + proj_b  (f32 out)
    hgemm<<<dim3(B_ * N_ / 128, 3), 256, gemm_smem>>>(
        pav, pwtp, pjb, out, nullptr, B_ * N_, DIM_, DIM_);
}

// round 15
// speedup vs baseline: 5.7076x; 1.2649x over previous
// R15 resubmit of audited R10-fix kernel (rounds 11-14 were broker failures).
#include <cuda_runtime.h>
#include <cuda_fp16.h>
#include <math.h>
#include <cstdint>

#define B_    32
#define N_    3136
#define DIM_  320
#define CN_   400
#define HEADS_ 5
#define NK_   196
#define DQ_   80
#define DV_   64
#define AQ_   128

// ---------------- scratch (static device globals; no runtime allocation) ----
__device__ __align__(16) __half g_xh[B_ * N_  * DIM_];
__device__ __align__(16) __half g_dw[B_ * NK_ * DIM_];     // dwconv out
__device__ __align__(16) float  g_pre[B_ * NK_ * CN_];     // pointwise out (pre-LN)
__device__ __align__(16) __half g_xs[B_ * NK_ * CN_];
__device__ __align__(16) __half g_q [B_ * N_  * CN_];
__device__ __align__(16) __half g_kv[B_ * NK_ * 720];
__device__ __align__(16) __half g_av[B_ * N_  * DIM_];
__device__ __align__(16) __half g_wtq[CN_ * DIM_];
__device__ __align__(16) __half g_wtkv[720 * CN_];
__device__ __align__(16) __half g_wtp[DIM_ * DIM_];
__device__ __align__(16) __half g_wpw[CN_ * DIM_];         // pw weights fp16

// ---------------- helpers ----------------------------------------------------
__device__ __forceinline__ uint32_t smem_u32(const void* p) {
    uint32_t a;
    asm("{ .reg .u64 t; cvta.to.shared.u64 t, %1; cvt.u32.u64 %0, t; }"
        : "=r"(a) : "l"(p));
    return a;
}
#define CPA(dst, src, sz) \
    asm volatile("cp.async.cg.shared.global [%0], [%1], 16, %2;" \
        :: "r"(dst), "l"(src), "r"(sz))
#define CPC() asm volatile("cp.async.commit_group;" ::: "memory")
#define CPW(n) asm volatile("cp.async.wait_group %0;" :: "n"(n) : "memory")

__device__ __forceinline__ void ldsm4(uint32_t r[4], uint32_t a) {
    asm volatile("ldmatrix.sync.aligned.m8n8.x4.shared.b16 {%0,%1,%2,%3}, [%4];"
        : "=r"(r[0]), "=r"(r[1]), "=r"(r[2]), "=r"(r[3]) : "r"(a));
}
__device__ __forceinline__ void ldsm2(uint32_t r[2], uint32_t a) {
    asm volatile("ldmatrix.sync.aligned.m8n8.x2.shared.b16 {%0,%1}, [%2];"
        : "=r"(r[0]), "=r"(r[1]) : "r"(a));
}
__device__ __forceinline__ void ldsm1(uint32_t& r, uint32_t a) {
    asm volatile("ldmatrix.sync.aligned.m8n8.x1.shared.b16 {%0}, [%1];"
        : "=r"(r) : "r"(a));
}
__device__ __forceinline__ void ldsm4t(uint32_t r[4], uint32_t a) {
    asm volatile("ldmatrix.sync.aligned.m8n8.x4.trans.shared.b16 {%0,%1,%2,%3}, [%4];"
        : "=r"(r[0]), "=r"(r[1]), "=r"(r[2]), "=r"(r[3]) : "r"(a));
}

__device__ __forceinline__ void mma16(float c[4],
                                      uint32_t a0, uint32_t a1, uint32_t a2, uint32_t a3,
                                      uint32_t b0, uint32_t b1) {
    asm volatile(
        "mma.sync.aligned.m16n8k16.row.col.f32.f16.f16.f32 "
        "{%0,%1,%2,%3}, {%4,%5,%6,%7}, {%8,%9}, {%0,%1,%2,%3};"
        : "+f"(c[0]), "+f"(c[1]), "+f"(c[2]), "+f"(c[3])
        : "r"(a0), "r"(a1), "r"(a2), "r"(a3), "r"(b0), "r"(b1));
}
__device__ __forceinline__ void mma8k(float c[4], uint32_t a0, uint32_t a1, uint32_t b0) {
    asm volatile(
        "mma.sync.aligned.m16n8k8.row.col.f32.f16.f16.f32 "
        "{%0,%1,%2,%3}, {%4,%5}, {%6}, {%0,%1,%2,%3};"
        : "+f"(c[0]), "+f"(c[1]), "+f"(c[2]), "+f"(c[3])
        : "r"(a0), "r"(a1), "r"(b0));
}
__device__ __forceinline__ uint32_t packh2(float a, float b) {
    __half2 h = __floats2half2_rn(a, b);
    return *reinterpret_cast<uint32_t*>(&h);
}
__inline__ __device__ float warp_sum(float v) {
#pragma unroll
    for (int o = 16; o; o >>= 1) v += __shfl_xor_sync(0xffffffffu, v, o);
    return v;
}

// ---------------- dwconv + x->fp16 (single fused pass over x) ----------------
__global__ __launch_bounds__(256) void dwcvt_kernel(
    const float* __restrict__ x, const float* __restrict__ dww,
    const float* __restrict__ dwb)
{
    int b  = blockIdx.x / NK_;
    int p  = blockIdx.x % NK_;
    int oh = p / 14, ow = p % 14;
    __shared__ float sp[16 * DIM_];

    int tid = threadIdx.x;
    const float* xb = x + (size_t)b * N_ * DIM_;
    __half* xhb = g_xh + (size_t)b * N_ * DIM_;
    for (int idx = tid; idx < 16 * DIM_; idx += 256) {
        int i = idx / DIM_, c = idx - i * DIM_;
        int n = (oh * 4 + (i >> 2)) * 56 + (ow * 4 + (i & 3));
        float v = xb[(size_t)n * DIM_ + c];
        sp[i * DIM_ + c] = v;
        xhb[(size_t)n * DIM_ + c] = __float2half_rn(v);
    }
    __syncthreads();
    for (int c = tid; c < DIM_; c += 256) {
        float acc = dwb[c];
#pragma unroll
        for (int i = 0; i < 16; i++)
            acc = fmaf(sp[i * DIM_ + c], dww[c * 16 + i], acc);
        g_dw[(size_t)blockIdx.x * DIM_ + c] = __float2half_rn(acc);
    }
}

// ---------------- weight prep ------------------------------------------------
__global__ void transpose_all(const float* __restrict__ qw, const float* __restrict__ kw,
                              const float* __restrict__ vw, const float* __restrict__ pjw,
                              const float* __restrict__ pww)
{
    int k = blockIdx.x * 256 + threadIdx.x;
    int n = blockIdx.y;
    int which = blockIdx.z;
    if (which == 0) {
        if (k < DIM_ && n < CN_) g_wtq[(size_t)n * DIM_ + k] = __float2half_rn(qw[(size_t)k * CN_ + n]);
    } else if (which == 1) {
        if (k < CN_ && n < CN_)  g_wtkv[(size_t)n * CN_ + k] = __float2half_rn(kw[(size_t)k * CN_ + n]);
    } else if (which == 2) {
        if (k < CN_ && n < DIM_) g_wtkv[(size_t)(400 + n) * CN_ + k] = __float2half_rn(vw[(size_t)k * DIM_ + n]);
    } else if (which == 3) {
        if (k < DIM_ && n < DIM_) g_wtp[(size_t)n * DIM_ + k] = __float2half_rn(pjw[(size_t)k * DIM_ + n]);
    } else {
        if (k < DIM_ && n < CN_) g_wpw[(size_t)n * DIM_ + k] = __float2half_rn(pww[(size_t)n * DIM_ + k]);
    }
}

// ---------------- LN + GELU: g_pre -> g_xs -----------------------------------
__global__ __launch_bounds__(128) void lngelu_kernel(
    const float* __restrict__ lng, const float* __restrict__ lnb)
{
    __shared__ float r1[4], r2[4];
    int r = blockIdx.x, tid = threadIdx.x, lane = tid & 31, w = tid >> 5;
    const float* row = g_pre + (size_t)r * CN_;
    float v[4];
    float s1 = 0.f, s2 = 0.f;
#pragma unroll
    for (int i = 0; i < 4; i++) {
        int c = tid + i * 128;
        v[i] = (c < CN_) ? row[c] : 0.f;
        s1 += v[i]; s2 += v[i] * v[i];
    }
    s1 = warp_sum(s1); s2 = warp_sum(s2);
    if (lane == 0) { r1[w] = s1; r2[w] = s2; }
    __syncthreads();
    float a = r1[0] + r1[1] + r1[2] + r1[3];
    float bq = r2[0] + r2[1] + r2[2] + r2[3];
    float mu = a / (float)CN_;
    float rstd = rsqrtf(bq / (float)CN_ - mu * mu + 1e-5f);
#pragma unroll
    for (int i = 0; i < 4; i++) {
        int c = tid + i * 128;
        if (c < CN_) {
            float y = (v[i] - mu) * rstd * lng[c] + lnb[c];
            float g = 0.5f * y * (1.f + erff(y * 0.70710678118654752f));
            g_xs[(size_t)r * CN_ + c] = __float2half_rn(g);
        }
    }
}

// ---------------- fp16 HMMA GEMM: BM=128, BN=80, BK=64, 3-stage --------------
#define HSTR 72
#define ATILE (128 * HSTR)
#define BTILE (80 * HSTR)
#define STAGEB ((ATILE + BTILE) * 2)
__global__ __launch_bounds__(256, 2) void hgemm(
    const __half* __restrict__ A, const __half* __restrict__ Bt,
    const float* __restrict__ bias, float* __restrict__ Cf,
    __half* __restrict__ Ch, int M, int N, int K)
{
    extern __shared__ __half hsm[];
    uint32_t sbase = smem_u32(hsm);

    int tid = threadIdx.x;
    int lane = tid & 31, w = tid >> 5;
    int g = lane >> 2, t = lane & 3;
    int lrow = lane & 15, lkh = lane >> 4;
    int row0 = blockIdx.x * 128, n0 = blockIdx.y * 80;
    int wm = (w & 3) * 32, wn = (w >> 2) * 40;
    int nIter = (K + 63) / 64;

    float acc[2][5][4] = {};

    auto load_stage = [&](int s, int k0) {
        uint32_t base = sbase + s * STAGEB;
#pragma unroll
        for (int it = 0; it < 4; it++) {
            int gr = tid + it * 256;
            int r = gr >> 3, c8 = (gr & 7) << 3;
            int kk = k0 + c8;
            const __half* sa = A + (size_t)(row0 + r) * K + (kk < K ? kk : 0);
            CPA(base + (r * HSTR + c8) * 2, sa, (kk < K) ? 16 : 0);
        }
#pragma unroll
        for (int it = 0; it < 3; it++) {
            int gr = tid + it * 256;
            if (gr < 640) {
                int r = gr >> 3, c8 = (gr & 7) << 3;
                int kk = k0 + c8;
                const __half* sb = Bt + (size_t)(n0 + r) * K + (kk < K ? kk : 0);
                CPA(base + ATILE * 2 + (r * HSTR + c8) * 2, sb, (kk < K) ? 16 : 0);
            }
        }
        CPC();
    };

    load_stage(0, 0);
    load_stage(1, 64);
    for (int i = 0; i < nIter; i++) {
        if (i + 2 < nIter) { load_stage((i + 2) % 3, (i + 2) * 64); CPW(2); }
        else CPW(0);
        __syncthreads();

        uint32_t sbA = sbase + (i % 3) * STAGEB;
        uint32_t sbB = sbA + ATILE * 2;
#pragma unroll
        for (int ks = 0; ks < 4; ks++) {
            uint32_t af[2][4], q0[4], q1[4], e2[2];
#pragma unroll
            for (int mi = 0; mi < 2; mi++)
                ldsm4(af[mi], sbA + ((wm + mi * 16 + lrow) * HSTR + ks * 16 + lkh * 8) * 2);
            ldsm4(q0, sbB + ((wn + lane) * HSTR + ks * 16 + 0) * 2);
            ldsm4(q1, sbB + ((wn + lane) * HSTR + ks * 16 + 8) * 2);
            ldsm2(e2, sbB + ((wn + 32 + (lane & 7)) * HSTR + ks * 16 + ((lane >> 3) & 1) * 8) * 2);
#pragma unroll
            for (int mi = 0; mi < 2; mi++) {
#pragma unroll
                for (int nj = 0; nj < 4; nj++)
                    mma16(acc[mi][nj], af[mi][0], af[mi][1], af[mi][2], af[mi][3],
                          q0[nj], q1[nj]);
                mma16(acc[mi][4], af[mi][0], af[mi][1], af[mi][2], af[mi][3],
                      e2[0], e2[1]);
            }
        }
        __syncthreads();
    }

#pragma unroll
    for (int mi = 0; mi < 2; mi++)
#pragma unroll
        for (int nj = 0; nj < 5; nj++) {
            int r = row0 + wm + mi * 16 + g;
            int c = n0 + wn + nj * 8 + 2 * t;
            if (Ch) {
                *reinterpret_cast<__half2*>(Ch + (size_t)r * N + c) =
                    __floats2half2_rn(acc[mi][nj][0], acc[mi][nj][1]);
                *reinterpret_cast<__half2*>(Ch + (size_t)(r + 8) * N + c) =
                    __floats2half2_rn(acc[mi][nj][2], acc[mi][nj][3]);
            } else {
                float b0 = bias ? bias[c]     : 0.f;
                float b1 = bias ? bias[c + 1] : 0.f;
                *reinterpret_cast<float2*>(Cf + (size_t)r * N + c) =
                    make_float2(acc[mi][nj][0] + b0, acc[mi][nj][1] + b1);
                *reinterpret_cast<float2*>(Cf + (size_t)(r + 8) * N + c) =
                    make_float2(acc[mi][nj][2] + b0, acc[mi][nj][3] + b1);
            }
        }
}

// ---------------- fused attention (128 queries, P-in-register split-K) -------
#define SQST 88
#define SKST 88
#define SVST 72
#define SOST 68
#define OQ   0
#define OK_  11264
#define OV   30976
#define OF32 47104
#define ATTN_SMEM (OF32 * 2 + (128 * SOST + 512 + 512 + 128) * 4)
__global__ __launch_bounds__(512, 1) void attn_kernel(float scale)
{
    extern __shared__ __half hs[];
    float* sO   = reinterpret_cast<float*>(hs + OF32);
    float* pmax = sO + 128 * SOST;
    float* psum = pmax + 512;
    float* srcp = psum + 512;

    int qt = blockIdx.x, h = blockIdx.y, b = blockIdx.z;
    int q0 = qt * AQ_;
    int tid = threadIdx.x;
    int lane = tid & 31, w = tid >> 5;
    int g = lane >> 2, t = lane & 3;
    int lrow = lane & 15, lkh = lane >> 4;
    int rg = w & 3, wg = w >> 2;
    int mp = rg * 32, nqk = wg * 56;

    for (int i = tid; i < 128 * SOST; i += 512) sO[i] = 0.f;

    {
        const __half* qb = g_q + ((size_t)(b * N_) + q0) * CN_ + h * DQ_;
        for (int idx = tid; idx < AQ_ * 10; idx += 512) {
            int r = idx / 10, c8 = (idx % 10) * 8;
            uint4 v = make_uint4(0, 0, 0, 0);
            if (q0 + r < N_) v = *reinterpret_cast<const uint4*>(qb + (size_t)r * CN_ + c8);
            *reinterpret_cast<uint4*>(hs + OQ + r * SQST + c8) = v;
        }
        const __half* kb = g_kv + (size_t)b * NK_ * 720 + h * DQ_;
        for (int idx = tid; idx < 224 * 10; idx += 512) {
            int j = idx / 10, c8 = (idx % 10) * 8;
            uint4 v = make_uint4(0, 0, 0, 0);
            if (j < NK_) v = *reinterpret_cast<const uint4*>(kb + (size_t)j * 720 + c8);
            *reinterpret_cast<uint4*>(hs + OK_ + j * SKST + c8) = v;
        }
        const __half* vb = g_kv + (size_t)b * NK_ * 720 + 400 + h * DV_;
        for (int idx = tid; idx < 224 * 8; idx += 512) {
            int j = idx / 8, c8 = (idx % 8) * 8;
            uint4 v = make_uint4(0, 0, 0, 0);
            if (j < NK_) v = *reinterpret_cast<const uint4*>(vb + (size_t)j * 720 + c8);
            *reinterpret_cast<uint4*>(hs + OV + j * SVST + c8) = v;
        }
    }
    __syncthreads();

    float acc[2][7][4] = {};
    {
        uint32_t sQb = smem_u32(hs + OQ);
        uint32_t sKb = smem_u32(hs + OK_);
#pragma unroll
        for (int ks = 0; ks < 5; ks++) {
            uint32_t af[2][4];
#pragma unroll
            for (int mi = 0; mi < 2; mi++)
                ldsm4(af[mi], sQb + ((mp + mi * 16 + lrow) * SQST + ks * 16 + lkh * 8) * 2);
            uint32_t bf[7][2];
#pragma unroll
            for (int kh = 0; kh < 2; kh++) {
                uint32_t b4[4], b2[2], b1;
                ldsm4(b4, sKb + ((nqk + lane) * SKST + ks * 16 + kh * 8) * 2);
                ldsm2(b2, sKb + ((nqk + 32 + (lane & 15)) * SKST + ks * 16 + kh * 8) * 2);
                ldsm1(b1, sKb + ((nqk + 48 + (lane & 7)) * SKST + ks * 16 + kh * 8) * 2);
                bf[0][kh] = b4[0]; bf[1][kh] = b4[1]; bf[2][kh] = b4[2]; bf[3][kh] = b4[3];
                bf[4][kh] = b2[0]; bf[5][kh] = b2[1]; bf[6][kh] = b1;
            }
#pragma unroll
            for (int mi = 0; mi < 2; mi++)
#pragma unroll
                for (int nj = 0; nj < 7; nj++)
                    mma16(acc[mi][nj], af[mi][0], af[mi][1], af[mi][2], af[mi][3],
                          bf[nj][0], bf[nj][1]);
        }
    }

#pragma unroll
    for (int mi = 0; mi < 2; mi++) {
        float ma = -1e30f, mb = -1e30f;
#pragma unroll
        for (int nj = 0; nj < 7; nj++) {
            int c = nqk + nj * 8 + 2 * t;
            if (c < NK_) {
                ma = fmaxf(ma, fmaxf(acc[mi][nj][0], acc[mi][nj][1]) * scale);
                mb = fmaxf(mb, fmaxf(acc[mi][nj][2], acc[mi][nj][3]) * scale);
            }
        }
#pragma unroll
        for (int o = 1; o <= 2; o <<= 1) {
            ma = fmaxf(ma, __shfl_xor_sync(0xffffffffu, ma, o));
            mb = fmaxf(mb, __shfl_xor_sync(0xffffffffu, mb, o));
        }
        if (t == 0) {
            pmax[(mp + mi * 16 + g) * 4 + wg]     = ma;
            pmax[(mp + mi * 16 + 8 + g) * 4 + wg] = mb;
        }
    }
    __syncthreads();

#pragma unroll
    for (int mi = 0; mi < 2; mi++) {
        int rA = mp + mi * 16 + g, rB = rA + 8;
        float ma = fmaxf(fmaxf(pmax[rA * 4], pmax[rA * 4 + 1]),
                         fmaxf(pmax[rA * 4 + 2], pmax[rA * 4 + 3]));
        float mb = fmaxf(fmaxf(pmax[rB * 4], pmax[rB * 4 + 1]),
                         fmaxf(pmax[rB * 4 + 2], pmax[rB * 4 + 3]));
        float sa = 0.f, sb = 0.f;
#pragma unroll
        for (int nj = 0; nj < 7; nj++) {
            int c = nqk + nj * 8 + 2 * t;
            if (c < NK_) {
                float e0 = __expf(acc[mi][nj][0] * scale - ma);
                float e1 = __expf(acc[mi][nj][1] * scale - ma);
                float e2 = __expf(acc[mi][nj][2] * scale - mb);
                float e3 = __expf(acc[mi][nj][3] * scale - mb);
                acc[mi][nj][0] = e0; acc[mi][nj][1] = e1;
                acc[mi][nj][2] = e2; acc[mi][nj][3] = e3;
                sa += e0 + e1; sb += e2 + e3;
            } else {
                acc[mi][nj][0] = acc[mi][nj][1] = 0.f;
                acc[mi][nj][2] = acc[mi][nj][3] = 0.f;
            }
        }
#pragma unroll
        for (int o = 1; o <= 2; o <<= 1) {
            sa += __shfl_xor_sync(0xffffffffu, sa, o);
            sb += __shfl_xor_sync(0xffffffffu, sb, o);
        }
        if (t == 0) { psum[rA * 4 + wg] = sa; psum[rB * 4 + wg] = sb; }
    }

    uint32_t ppa[2][7], ppb[2][7];
#pragma unroll
    for (int mi = 0; mi < 2; mi++)
#pragma unroll
        for (int nj = 0; nj < 7; nj++) {
            ppa[mi][nj] = packh2(acc[mi][nj][0], acc[mi][nj][1]);
            ppb[mi][nj] = packh2(acc[mi][nj][2], acc[mi][nj][3]);
        }
    __syncthreads();

    if (tid < AQ_)
        srcp[tid] = 1.f / (psum[tid * 4] + psum[tid * 4 + 1] +
                           psum[tid * 4 + 2] + psum[tid * 4 + 3]);

    {
        uint32_t sVb = smem_u32(hs + OV);
#pragma unroll
        for (int vh = 0; vh < 2; vh++) {
            float o[2][4][4] = {};
#pragma unroll
            for (int ks = 0; ks < 7; ks++) {
                uint32_t bt[4];
                ldsm4t(bt, sVb + ((nqk + ks * 8 + (lane & 7)) * SVST
                                  + vh * 32 + (lane >> 3) * 8) * 2);
#pragma unroll
                for (int mi = 0; mi < 2; mi++)
#pragma unroll
                    for (int nj = 0; nj < 4; nj++)
                        mma8k(o[mi][nj], ppa[mi][ks], ppb[mi][ks], bt[nj]);
            }
#pragma unroll
            for (int mi = 0; mi < 2; mi++)
#pragma unroll
                for (int nj = 0; nj < 4; nj++) {
                    int row = mp + mi * 16 + g;
                    int col = vh * 32 + nj * 8 + 2 * t;
                    atomicAdd(&sO[row * SOST + col],           o[mi][nj][0]);
                    atomicAdd(&sO[row * SOST + col + 1],       o[mi][nj][1]);
                    atomicAdd(&sO[(row + 8) * SOST + col],     o[mi][nj][2]);
                    atomicAdd(&sO[(row + 8) * SOST + col + 1], o[mi][nj][3]);
                }
        }
    }
    __syncthreads();

    for (int idx = tid; idx < AQ_ * 32; idx += 512) {
        int r = idx >> 5, c2 = idx & 31;
        if (q0 + r < N_) {
            float rc = srcp[r];
            float o0 = sO[r * SOST + 2 * c2]     * rc;
            float o1 = sO[r * SOST + 2 * c2 + 1] * rc;
            *reinterpret_cast<__half2*>(
                g_av + ((size_t)(b * N_) + q0 + r) * DIM_ + h * DV_ + 2 * c2) =
                __floats2half2_rn(o0, o1);
        }
    }
}

// ---------------- launch -----------------------------------------------------
extern "C" void kernel_launch(void* const* d_in, const int* in_sizes, int n_in,
                              void* d_out, int out_size)
{
    const float* x   = (const float*)d_in[0];
    const float* dww = (const float*)d_in[3];
    const float* dwb = (const float*)d_in[4];
    const float* pww = (const float*)d_in[5];
    const float* pwb = (const float*)d_in[6];
    const float* lng = (const float*)d_in[7];
    const float* lnb = (const float*)d_in[8];
    const float* qw  = (const float*)d_in[9];
    const float* kw  = (const float*)d_in[10];
    const float* vw  = (const float*)d_in[11];
    const float* pjw = (const float*)d_in[12];
    const float* pjb = (const float*)d_in[13];
    float* out = (float*)d_out;

    __half *pxh, *pdw, *pxs, *pq, *pkv, *pav, *pwtq, *pwtkv, *pwtp, *pwpw;
    float *ppre;
    cudaGetSymbolAddress((void**)&pxh,   g_xh);
    cudaGetSymbolAddress((void**)&pdw,   g_dw);
    cudaGetSymbolAddress((void**)&ppre,  g_pre);
    cudaGetSymbolAddress((void**)&pxs,   g_xs);
    cudaGetSymbolAddress((void**)&pq,    g_q);
    cudaGetSymbolAddress((void**)&pkv,   g_kv);
    cudaGetSymbolAddress((void**)&pav,   g_av);
    cudaGetSymbolAddress((void**)&pwtq,  g_wtq);
    cudaGetSymbolAddress((void**)&pwtkv, g_wtkv);
    cudaGetSymbolAddress((void**)&pwtp,  g_wtp);
    cudaGetSymbolAddress((void**)&pwpw,  g_wpw);

    dwcvt_kernel<<<B_ * NK_, 256>>>(x, dww, dwb);
    transpose_all<<<dim3(2, CN_, 5), 256>>>(qw, kw, vw, pjw, pww);

    const int gemm_smem = 3 * STAGEB;   // 89856 B
    cudaFuncSetAttribute(hgemm, cudaFuncAttributeMaxDynamicSharedMemorySize, gemm_smem);

    // pointwise conv as GEMM: pre = dw @ pw^T + pwb : [6272, 400] f32
    hgemm<<<dim3(B_ * NK_ / 128, CN_ / 80), 256, gemm_smem>>>(
        pdw, pwpw, pwb, ppre, nullptr, B_ * NK_, CN_, DIM_);

    lngelu_kernel<<<B_ * NK_, 128>>>(lng, lnb);

    // q = x @ q_w : [100352, 400]
    hgemm<<<dim3(B_ * N_ / 128, CN_ / 80), 256, gemm_smem>>>(
        pxh, pwtq, nullptr, nullptr, pq, B_ * N_, CN_, DIM_);

    // kv = xs @ [k_w | v_w] : [6272, 720]
    hgemm<<<dim3(B_ * NK_ / 128, 720 / 80), 256, gemm_smem>>>(
        pxs, pwtkv, nullptr, nullptr, pkv, B_ * NK_, 720, CN_);

    cudaFuncSetAttribute(attn_kernel,
                         cudaFuncAttributeMaxDynamicSharedMemorySize, ATTN_SMEM);
    attn_kernel<<<dim3((N_ + AQ_ - 1) / AQ_, HEADS_, B_), 512, ATTN_SMEM>>>(
        0.11180339887498949f /* 80^-0.5 */);

    // out = av @ proj_w + proj_b  (f32 out)
    hgemm<<<dim3(B_ * N_ / 128, DIM_ / 80), 256, gemm_smem>>>(
        pav, pwtp, pjb, out, nullptr, B_ * N_, DIM_, DIM_);
}